// round 7
// baseline (speedup 1.0000x reference)
#include <cuda_runtime.h>
#include <stdint.h>
#include <math.h>
#include <algorithm>

#define Bsz 1024
#define Tt  200
#define Dd  512
#define Hh  256
#define KK  12
#define KMI 30
#define G3H 768
#define NSCAN 141

// ---------------- scratch ----------------------------------------------------
__device__ float g_xproj[(size_t)Tt * Bsz * G3H];  // [T][B][3H]
__device__ float g_whht[(size_t)Hh * G3H];         // [k][3H] transposed w_hh
__device__ float g_hA[Bsz * Hh];
__device__ float g_centers[KK * Hh];
__device__ float g_hprime[KK * Hh];
__device__ int   g_codes[Bsz];
__device__ int   g_order[Bsz];    // row indices sorted by length desc

struct IdxList { int v[KK]; };

__global__ void k_init() {
    int idx = blockIdx.x * blockDim.x + threadIdx.x;
    if (idx < Bsz * Hh) g_hA[idx] = 0.0f;
}

// ---------------- transpose w_hh: [3H][H] -> [H][3H] -------------------------
__global__ void k_trans(const float* __restrict__ w_hh) {
    int idx = blockIdx.x * 256 + threadIdx.x;
    if (idx < G3H * Hh) {
        int g = idx / Hh, k = idx - g * Hh;
        g_whht[(size_t)k * G3H + g] = w_hh[idx];
    }
}

// ---------------- rank-sort rows by length desc -------------------------------
__global__ void k_sort(const int* __restrict__ lengths) {
    __shared__ int ls[Bsz];
    int tid = threadIdx.x;
    for (int i = tid; i < Bsz; i += 256) ls[i] = lengths[i];
    __syncthreads();
    for (int i = tid; i < Bsz; i += 256) {
        int li = ls[i];
        int r = 0;
        for (int b = 0; b < Bsz; b++) {
            int lb = ls[b];
            r += (lb > li) || (lb == li && b < i);
        }
        g_order[r] = i;
    }
}

// ---------------- tf32 helpers ------------------------------------------------
__device__ __forceinline__ uint32_t f2tf32(float f) {
    uint32_t r;
    asm("cvt.rna.tf32.f32 %0, %1;" : "=r"(r) : "f"(f));
    return r;
}
__device__ __forceinline__ void split_tf32(float f, uint32_t& hi, uint32_t& lo) {
    hi = f2tf32(f);
    lo = f2tf32(f - __uint_as_float(hi));
}
__device__ __forceinline__ void mma_tf32(float* c, const uint32_t* a,
                                         const uint32_t* b) {
    asm volatile(
        "mma.sync.aligned.m16n8k8.row.col.f32.tf32.tf32.f32 "
        "{%0,%1,%2,%3}, {%4,%5,%6,%7}, {%8,%9}, {%0,%1,%2,%3};"
        : "+f"(c[0]), "+f"(c[1]), "+f"(c[2]), "+f"(c[3])
        : "r"(a[0]), "r"(a[1]), "r"(a[2]), "r"(a[3]), "r"(b[0]), "r"(b[1]));
}

// ---------------- x-projection GEMM (tensor cores, 3xTF32) -------------------
// C[m,n] = sum_d x[m,d]*w_ih[n,d] + b_ih[n]; m = b*T + t; out g_xproj[t][b][n].
// Tile 128x64, BK=16, 8 warps in 4(m) x 2(n); warp tile 32x32 via m16n8k8.
__global__ void __launch_bounds__(256) k_xproj(const float* __restrict__ x,
                                               const float* __restrict__ w_ih,
                                               const float* __restrict__ b_ih,
                                               const int* __restrict__ lengths) {
    const int m0 = blockIdx.y * 128;
    const int n0 = blockIdx.x * 64;

    {   // skip block if no covered (b,t) is ever consumed
        int b_first = m0 / Tt, b_last = (m0 + 127) / Tt;
        bool need = false;
        for (int b = b_first; b <= b_last && b < Bsz; b++) {
            int t_start = (m0 > b * Tt) ? (m0 - b * Tt) : 0;
            if (lengths[b] > t_start) need = true;
        }
        if (!need) return;
    }

    __shared__ uint32_t Ah[16][132], Al[16][132];
    __shared__ uint32_t Bh[16][68],  Bl[16][68];

    const int tid = threadIdx.x;
    const int lr = tid >> 2, lc4 = tid & 3;
    const int wid = tid >> 5, lane = tid & 31;
    const int wm = (wid & 3) * 32;   // warp row offset in 128-tile
    const int wn = (wid >> 2) * 32;  // warp col offset in 64-tile
    const int lq = lane >> 2, lc = lane & 3;

    float c[2][4][4];
#pragma unroll
    for (int mf = 0; mf < 2; mf++)
#pragma unroll
        for (int nf = 0; nf < 4; nf++)
#pragma unroll
            for (int q = 0; q < 4; q++) c[mf][nf][q] = 0.0f;

    for (int k0 = 0; k0 < Dd; k0 += 16) {
        // stage A (128x16) hi/lo, layout [k][m]
#pragma unroll
        for (int it = 0; it < 2; it++) {
            int r = lr + it * 64;
            float4 v = *reinterpret_cast<const float4*>(
                &x[(size_t)(m0 + r) * Dd + k0 + lc4 * 4]);
            uint32_t h, l;
            split_tf32(v.x, h, l); Ah[lc4 * 4 + 0][r] = h; Al[lc4 * 4 + 0][r] = l;
            split_tf32(v.y, h, l); Ah[lc4 * 4 + 1][r] = h; Al[lc4 * 4 + 1][r] = l;
            split_tf32(v.z, h, l); Ah[lc4 * 4 + 2][r] = h; Al[lc4 * 4 + 2][r] = l;
            split_tf32(v.w, h, l); Ah[lc4 * 4 + 3][r] = h; Al[lc4 * 4 + 3][r] = l;
        }
        // stage B (64x16) hi/lo, layout [k][n]
        {
            float4 v = *reinterpret_cast<const float4*>(
                &w_ih[(size_t)(n0 + lr) * Dd + k0 + lc4 * 4]);
            uint32_t h, l;
            split_tf32(v.x, h, l); Bh[lc4 * 4 + 0][lr] = h; Bl[lc4 * 4 + 0][lr] = l;
            split_tf32(v.y, h, l); Bh[lc4 * 4 + 1][lr] = h; Bl[lc4 * 4 + 1][lr] = l;
            split_tf32(v.z, h, l); Bh[lc4 * 4 + 2][lr] = h; Bl[lc4 * 4 + 2][lr] = l;
            split_tf32(v.w, h, l); Bh[lc4 * 4 + 3][lr] = h; Bl[lc4 * 4 + 3][lr] = l;
        }
        __syncthreads();

#pragma unroll
        for (int ks = 0; ks < 2; ks++) {
            const int kb = ks * 8;
            // A fragments: a0=(r,c) a1=(r+8,c) a2=(r,c+4) a3=(r+8,c+4)
            uint32_t ah[2][4], al[2][4];
#pragma unroll
            for (int mf = 0; mf < 2; mf++) {
                int r = wm + mf * 16 + lq;
                ah[mf][0] = Ah[kb + lc][r];     al[mf][0] = Al[kb + lc][r];
                ah[mf][1] = Ah[kb + lc][r + 8]; al[mf][1] = Al[kb + lc][r + 8];
                ah[mf][2] = Ah[kb + lc + 4][r];     al[mf][2] = Al[kb + lc + 4][r];
                ah[mf][3] = Ah[kb + lc + 4][r + 8]; al[mf][3] = Al[kb + lc + 4][r + 8];
            }
            // B fragments: b0=(k,n)=(c,q) b1=(c+4,q)
            uint32_t bh[4][2], bl[4][2];
#pragma unroll
            for (int nf = 0; nf < 4; nf++) {
                int n = wn + nf * 8 + lq;
                bh[nf][0] = Bh[kb + lc][n];     bl[nf][0] = Bl[kb + lc][n];
                bh[nf][1] = Bh[kb + lc + 4][n]; bl[nf][1] = Bl[kb + lc + 4][n];
            }
#pragma unroll
            for (int mf = 0; mf < 2; mf++)
#pragma unroll
                for (int nf = 0; nf < 4; nf++) {
                    mma_tf32(c[mf][nf], ah[mf], bh[nf]);  // hi*hi
                    mma_tf32(c[mf][nf], ah[mf], bl[nf]);  // hi*lo
                    mma_tf32(c[mf][nf], al[mf], bh[nf]);  // lo*hi
                }
        }
        __syncthreads();
    }

    // epilogue: c0,c1 -> row r, cols 2lc,2lc+1; c2,c3 -> row r+8
#pragma unroll
    for (int mf = 0; mf < 2; mf++)
#pragma unroll
        for (int half = 0; half < 2; half++) {
            int row = m0 + wm + mf * 16 + lq + half * 8;
            int b = row / Tt;
            int t = row - b * Tt;
            size_t base = ((size_t)t * Bsz + b) * G3H + n0 + wn;
#pragma unroll
            for (int nf = 0; nf < 4; nf++) {
                int col = nf * 8 + lc * 2;
                float2 o;
                o.x = c[mf][nf][half * 2 + 0] + b_ih[n0 + wn + col];
                o.y = c[mf][nf][half * 2 + 1] + b_ih[n0 + wn + col + 1];
                *reinterpret_cast<float2*>(&g_xproj[base + col]) = o;
            }
        }
}

// ---------------- persistent GRU scan ----------------------------------------
template <int R>
__device__ void scan_body(float (*hs)[Hh], int start,
                          const float* __restrict__ b_hh,
                          const int* __restrict__ lengths) {
    const int j = threadIdx.x;

    int rows[R], lens[R];
#pragma unroll
    for (int i = 0; i < R; i++) {
        int p = start + i;
        rows[i] = (p < Bsz) ? g_order[p] : 0;
        lens[i] = (p < Bsz) ? lengths[rows[i]] : 0;
    }
#pragma unroll
    for (int i = 0; i < R; i++) hs[i][j] = 0.0f;
    __syncthreads();

    int maxlen = 0;
#pragma unroll
    for (int i = 0; i < R; i++) maxlen = max(maxlen, lens[i]);

    const float bhr = b_hh[j], bhz = b_hh[Hh + j], bhn = b_hh[2 * Hh + j];

    for (int t = 0; t < maxlen; t++) {
        float ar[R], az[R], an[R];
#pragma unroll
        for (int i = 0; i < R; i++) { ar[i] = 0.f; az[i] = 0.f; an[i] = 0.f; }

        for (int k = 0; k < Hh; k++) {
            const float* wp = &g_whht[(size_t)k * G3H + j];
            float wr = wp[0], wz = wp[Hh], wn = wp[2 * Hh];
#pragma unroll
            for (int i = 0; i < R; i++) {
                float h = hs[i][k];
                ar[i] = fmaf(h, wr, ar[i]);
                az[i] = fmaf(h, wz, az[i]);
                an[i] = fmaf(h, wn, an[i]);
            }
        }

        float hnew[R];
#pragma unroll
        for (int i = 0; i < R; i++) {
            float hold = hs[i][j];
            if (t < lens[i]) {
                const float* xp = &g_xproj[((size_t)t * Bsz + rows[i]) * G3H + j];
                float r = 1.0f / (1.0f + expf(-(xp[0] + ar[i] + bhr)));
                float z = 1.0f / (1.0f + expf(-(xp[Hh] + az[i] + bhz)));
                float n = tanhf(xp[2 * Hh] + r * (an[i] + bhn));
                hnew[i] = (1.0f - z) * n + z * hold;
            } else {
                hnew[i] = hold;
            }
        }
        __syncthreads();
#pragma unroll
        for (int i = 0; i < R; i++) hs[i][j] = hnew[i];
        __syncthreads();
    }

#pragma unroll
    for (int i = 0; i < R; i++)
        if (start + i < Bsz)
            g_hA[(size_t)rows[i] * Hh + j] = hs[i][j];
}

__global__ void __launch_bounds__(256, 1) k_scan(const float* __restrict__ b_hh,
                                                 const int* __restrict__ lengths) {
    __shared__ float hs[16][Hh];
    int bb = blockIdx.x;
    if (bb < 48)        scan_body<4>(hs, 4 * bb, b_hh, lengths);
    else if (bb < 80)   scan_body<6>(hs, 192 + 6 * (bb - 48), b_hh, lengths);
    else if (bb < 108)  scan_body<8>(hs, 384 + 8 * (bb - 80), b_hh, lengths);
    else if (bb < 128)  scan_body<11>(hs, 608 + 11 * (bb - 108), b_hh, lengths);
    else                scan_body<16>(hs, 828 + 16 * (bb - 128), b_hh, lengths);
}

// ---------------- kmeans -----------------------------------------------------
__global__ void k_cinit(IdxList il) {
    int d = threadIdx.x;
#pragma unroll
    for (int k = 0; k < KK; k++)
        g_centers[k * Hh + d] = g_hA[(size_t)il.v[k] * Hh + d];
}

__global__ void k_assign() {
    __shared__ float cs[KK * Hh];
    int tid = threadIdx.x;  // 128
    for (int i = tid; i < KK * Hh; i += 128) cs[i] = g_centers[i];
    __syncthreads();

    int warp = tid >> 5, lane = tid & 31;
    int b = blockIdx.x * 4 + warp;

    float dist[KK];
#pragma unroll
    for (int k = 0; k < KK; k++) dist[k] = 0.0f;
#pragma unroll
    for (int i = 0; i < 8; i++) {
        int d = lane + i * 32;
        float v = g_hA[(size_t)b * Hh + d];
#pragma unroll
        for (int k = 0; k < KK; k++) {
            float df = v - cs[k * Hh + d];
            dist[k] += df * df;
        }
    }
#pragma unroll
    for (int k = 0; k < KK; k++)
#pragma unroll
        for (int o = 16; o > 0; o >>= 1)
            dist[k] += __shfl_xor_sync(0xffffffffu, dist[k], o);

    int code = 0;
    float best = dist[0];
#pragma unroll
    for (int k = 1; k < KK; k++)
        if (dist[k] < best) { best = dist[k]; code = k; }
    if (lane == 0) g_codes[b] = code;
}

__global__ void k_update() {
    __shared__ int codes[Bsz];
    int k = blockIdx.x, d = threadIdx.x;
    for (int i = d; i < Bsz; i += 256) codes[i] = g_codes[i];
    __syncthreads();
    float s = 0.0f, cnt = 0.0f;
    for (int b = 0; b < Bsz; b++) {
        if (codes[b] == k) { s += g_hA[(size_t)b * Hh + d]; cnt += 1.0f; }
    }
    float cold = g_centers[k * Hh + d];
    g_centers[k * Hh + d] = (cnt > 0.0f) ? (s / fmaxf(cnt, 1.0f)) : cold;
}

// ---------------- GCN (adj = I -> per-center MLP) ----------------------------
__global__ void k_hprime(const float* __restrict__ g1w, const float* __restrict__ g1b,
                         const float* __restrict__ g2w, const float* __restrict__ g2b) {
    int k = blockIdx.x, j = threadIdx.x;
    __shared__ float c[Hh], tmp[Hh];
    c[j] = g_centers[k * Hh + j];
    __syncthreads();
    float s = g1b[j];
    for (int d = 0; d < Hh; d++) s += c[d] * g1w[(size_t)d * Hh + j];
    tmp[j] = fmaxf(s, 0.0f);
    __syncthreads();
    float s2 = g2b[j];
    for (int d = 0; d < Hh; d++) s2 += tmp[d] * g2w[(size_t)d * Hh + j];
    g_hprime[k * Hh + j] = fmaxf(s2, 0.0f);
}

// ---------------- epilogue ---------------------------------------------------
__global__ void k_epi(const float* __restrict__ wt1w, const float* __restrict__ wt1b,
                      const float* __restrict__ wt2w, const float* __restrict__ wt2b,
                      float* __restrict__ out) {
    __shared__ float cs[KK * Hh], hp[KK * Hh], w1s[Hh], w2s[Hh];
    int tid = threadIdx.x;  // 128
    for (int i = tid; i < KK * Hh; i += 128) { cs[i] = g_centers[i]; hp[i] = g_hprime[i]; }
    for (int i = tid; i < Hh; i += 128)      { w1s[i] = wt1w[i]; w2s[i] = wt2w[i]; }
    __syncthreads();

    int warp = tid >> 5, lane = tid & 31;
    int b = blockIdx.x * 4 + warp;

    float e[KK];
#pragma unroll
    for (int k = 0; k < KK; k++) e[k] = 0.0f;
    float hv[8];
#pragma unroll
    for (int i = 0; i < 8; i++) {
        int d = lane + i * 32;
        float v = g_hA[(size_t)b * Hh + d];
        hv[i] = v;
#pragma unroll
        for (int k = 0; k < KK; k++) e[k] += v * cs[k * Hh + d];
    }
#pragma unroll
    for (int k = 0; k < KK; k++)
#pragma unroll
        for (int o = 16; o > 0; o >>= 1)
            e[k] += __shfl_xor_sync(0xffffffffu, e[k], o);

    float mx = 0.0f;
#pragma unroll
    for (int k = 0; k < KK; k++) { e[k] = fmaxf(e[k], 0.0f); mx = fmaxf(mx, e[k]); }
    float den = 0.0f, sc[KK];
#pragma unroll
    for (int k = 0; k < KK; k++) { sc[k] = expf(e[k] - mx); den += sc[k]; }
    float inv = 1.0f / den;
#pragma unroll
    for (int k = 0; k < KK; k++) sc[k] *= inv;

    float w1p = 0.0f, w2p = 0.0f, cl[8];
#pragma unroll
    for (int i = 0; i < 8; i++) {
        int d = lane + i * 32;
        float s = 0.0f;
#pragma unroll
        for (int k = 0; k < KK; k++) s += sc[k] * hp[k * Hh + d];
        cl[i] = s;
        w1p += s * w1s[d];
        w2p += hv[i] * w2s[d];
    }
#pragma unroll
    for (int o = 16; o > 0; o >>= 1) {
        w1p += __shfl_xor_sync(0xffffffffu, w1p, o);
        w2p += __shfl_xor_sync(0xffffffffu, w2p, o);
    }
    float w1 = 1.0f / (1.0f + expf(-(w1p + wt1b[0])));
    float w2 = 1.0f / (1.0f + expf(-(w2p + wt2b[0])));
    float w1n = w1 / (w1 + w2 + 1e-8f);
#pragma unroll
    for (int i = 0; i < 8; i++) {
        int d = lane + i * 32;
        out[(size_t)b * Hh + d] = w1n * cl[i] + (1.0f - w1n) * hv[i];
    }
}

// ---------------- host: JAX threefry replication -----------------------------
static inline uint32_t rotl32(uint32_t v, int d) { return (v << d) | (v >> (32 - d)); }

static void threefry2x32(uint32_t k0, uint32_t k1, uint32_t c0, uint32_t c1,
                         uint32_t* o0, uint32_t* o1) {
    uint32_t ks0 = k0, ks1 = k1, ks2 = k0 ^ k1 ^ 0x1BD11BDAu;
    uint32_t x0 = c0 + ks0, x1 = c1 + ks1;
    const int rA[4] = {13, 15, 26, 6};
    const int rB[4] = {17, 29, 16, 24};
#define TF4(R) for (int i_ = 0; i_ < 4; i_++) { x0 += x1; x1 = rotl32(x1, R[i_]); x1 ^= x0; }
    TF4(rA); x0 += ks1; x1 += ks2 + 1u;
    TF4(rB); x0 += ks2; x1 += ks0 + 2u;
    TF4(rA); x0 += ks0; x1 += ks1 + 3u;
    TF4(rB); x0 += ks1; x1 += ks2 + 4u;
    TF4(rA); x0 += ks2; x1 += ks0 + 5u;
#undef TF4
    *o0 = x0; *o1 = x1;
}

static void compute_init_indices(int* out12) {
    uint32_t sk0, sk1;
    threefry2x32(0u, 42u, 0u, 1u, &sk0, &sk1);
    uint32_t keys[Bsz];
    for (int i = 0; i < Bsz; i++) {
        uint32_t o0, o1;
        threefry2x32(sk0, sk1, 0u, (uint32_t)i, &o0, &o1);
        keys[i] = o0 ^ o1;
    }
    int idx[Bsz];
    for (int i = 0; i < Bsz; i++) idx[i] = i;
    std::stable_sort(idx, idx + Bsz,
                     [&](int a, int b) { return keys[a] < keys[b]; });
    for (int k = 0; k < KK; k++) out12[k] = idx[k];
}

// ---------------- launch -----------------------------------------------------
extern "C" void kernel_launch(void* const* d_in, const int* in_sizes, int n_in,
                              void* d_out, int out_size) {
    const float* x       = (const float*)d_in[0];
    const int*   lengths = (const int*)  d_in[1];
    const float* w_ih    = (const float*)d_in[2];
    const float* w_hh    = (const float*)d_in[3];
    const float* b_ih    = (const float*)d_in[4];
    const float* b_hh    = (const float*)d_in[5];
    const float* g1w     = (const float*)d_in[6];
    const float* g1b     = (const float*)d_in[7];
    const float* g2w     = (const float*)d_in[8];
    const float* g2b     = (const float*)d_in[9];
    const float* wt1w    = (const float*)d_in[10];
    const float* wt1b    = (const float*)d_in[11];
    const float* wt2w    = (const float*)d_in[12];
    const float* wt2b    = (const float*)d_in[13];
    float* out = (float*)d_out;
    (void)in_sizes; (void)n_in; (void)out_size;

    IdxList il;
    compute_init_indices(il.v);

    k_init<<<1024, 256>>>();
    k_trans<<<(G3H * Hh + 255) / 256, 256>>>(w_hh);
    k_sort<<<1, 256>>>(lengths);
    k_xproj<<<dim3(12, 1600), 256>>>(x, w_ih, b_ih, lengths);
    k_scan<<<NSCAN, 256>>>(b_hh, lengths);
    k_cinit<<<1, 256>>>(il);
    for (int it = 0; it < KMI; it++) {
        k_assign<<<256, 128>>>();
        k_update<<<KK, 256>>>();
    }
    k_hprime<<<KK, 256>>>(g1w, g1b, g2w, g2b);
    k_epi<<<256, 128>>>(wt1w, wt1b, wt2w, wt2b, out);
}

// round 8
// speedup vs baseline: 1.1050x; 1.1050x over previous
#include <cuda_runtime.h>
#include <stdint.h>
#include <math.h>
#include <algorithm>

#define Bsz 1024
#define Tt  200
#define Dd  512
#define Hh  256
#define KK  12
#define KMI 30
#define G3H 768
#define NSCAN 141

// ---------------- scratch ----------------------------------------------------
__device__ float g_xproj[(size_t)Tt * Bsz * G3H];  // [T][B][3H]
// packed recurrence weights: g_wv4[(kq*3+g)*Hh + j] = w_hh[g*256+j][4kq..4kq+3]
__device__ float4 g_wv4[(Hh / 4) * 3 * Hh];
__device__ float g_hA[Bsz * Hh];
__device__ float g_centers[KK * Hh];
__device__ float g_hprime[KK * Hh];
__device__ int   g_codes[Bsz];
__device__ int   g_order[Bsz];    // row indices sorted by length desc

struct IdxList { int v[KK]; };

__global__ void k_init() {
    int idx = blockIdx.x * blockDim.x + threadIdx.x;
    if (idx < Bsz * Hh) g_hA[idx] = 0.0f;
}

// ---------------- repack w_hh: [3H][H] -> float4-blocked ---------------------
__global__ void k_trans(const float* __restrict__ w_hh) {
    int idx = blockIdx.x * 256 + threadIdx.x;
    if (idx < G3H * Hh) {
        int n = idx / Hh, k = idx - n * Hh;  // w_hh[n][k]
        int g = n >> 8, j = n & 255;
        int kq = k >> 2, kr = k & 3;
        reinterpret_cast<float*>(g_wv4)[(size_t)(((kq * 3) + g) * Hh + j) * 4 + kr] =
            w_hh[idx];
    }
}

// ---------------- rank-sort rows by length desc -------------------------------
__global__ void k_sort(const int* __restrict__ lengths) {
    __shared__ int ls[Bsz];
    int tid = threadIdx.x;
    for (int i = tid; i < Bsz; i += 256) ls[i] = lengths[i];
    __syncthreads();
    for (int i = tid; i < Bsz; i += 256) {
        int li = ls[i];
        int r = 0;
        for (int b = 0; b < Bsz; b++) {
            int lb = ls[b];
            r += (lb > li) || (lb == li && b < i);
        }
        g_order[r] = i;
    }
}

// ---------------- tf32 helpers ------------------------------------------------
__device__ __forceinline__ uint32_t f2tf32(float f) {
    uint32_t r;
    asm("cvt.rna.tf32.f32 %0, %1;" : "=r"(r) : "f"(f));
    return r;
}
__device__ __forceinline__ void split_tf32(float f, uint32_t& hi, uint32_t& lo) {
    hi = f2tf32(f);
    lo = f2tf32(f - __uint_as_float(hi));
}
__device__ __forceinline__ void mma_tf32(float* c, const uint32_t* a,
                                         const uint32_t* b) {
    asm volatile(
        "mma.sync.aligned.m16n8k8.row.col.f32.tf32.tf32.f32 "
        "{%0,%1,%2,%3}, {%4,%5,%6,%7}, {%8,%9}, {%0,%1,%2,%3};"
        : "+f"(c[0]), "+f"(c[1]), "+f"(c[2]), "+f"(c[3])
        : "r"(a[0]), "r"(a[1]), "r"(a[2]), "r"(a[3]), "r"(b[0]), "r"(b[1]));
}

// ---------------- x-projection GEMM (tensor cores, 3xTF32, fp32 smem) --------
__global__ void __launch_bounds__(256) k_xproj(const float* __restrict__ x,
                                               const float* __restrict__ w_ih,
                                               const float* __restrict__ b_ih,
                                               const int* __restrict__ lengths) {
    const int m0 = blockIdx.y * 128;
    const int n0 = blockIdx.x * 64;

    {   // skip block if no covered (b,t) is ever consumed
        int b_first = m0 / Tt, b_last = (m0 + 127) / Tt;
        bool need = false;
        for (int b = b_first; b <= b_last && b < Bsz; b++) {
            int t_start = (m0 > b * Tt) ? (m0 - b * Tt) : 0;
            if (lengths[b] > t_start) need = true;
        }
        if (!need) return;
    }

    __shared__ float As[16][132];   // fp32, split to tf32 in registers
    __shared__ float Bs[16][68];

    const int tid = threadIdx.x;
    const int lr = tid >> 2, lc4 = tid & 3;
    const int wid = tid >> 5, lane = tid & 31;
    const int wm = (wid & 3) * 32;
    const int wn = (wid >> 2) * 32;
    const int lq = lane >> 2, lc = lane & 3;

    float c[2][4][4];
#pragma unroll
    for (int mf = 0; mf < 2; mf++)
#pragma unroll
        for (int nf = 0; nf < 4; nf++)
#pragma unroll
            for (int q = 0; q < 4; q++) c[mf][nf][q] = 0.0f;

    for (int k0 = 0; k0 < Dd; k0 += 16) {
#pragma unroll
        for (int it = 0; it < 2; it++) {
            int r = lr + it * 64;
            float4 v = *reinterpret_cast<const float4*>(
                &x[(size_t)(m0 + r) * Dd + k0 + lc4 * 4]);
            As[lc4 * 4 + 0][r] = v.x; As[lc4 * 4 + 1][r] = v.y;
            As[lc4 * 4 + 2][r] = v.z; As[lc4 * 4 + 3][r] = v.w;
        }
        {
            float4 v = *reinterpret_cast<const float4*>(
                &w_ih[(size_t)(n0 + lr) * Dd + k0 + lc4 * 4]);
            Bs[lc4 * 4 + 0][lr] = v.x; Bs[lc4 * 4 + 1][lr] = v.y;
            Bs[lc4 * 4 + 2][lr] = v.z; Bs[lc4 * 4 + 3][lr] = v.w;
        }
        __syncthreads();

#pragma unroll
        for (int ks = 0; ks < 2; ks++) {
            const int kb = ks * 8;
            uint32_t ah[2][4], al[2][4];
#pragma unroll
            for (int mf = 0; mf < 2; mf++) {
                int r = wm + mf * 16 + lq;
                float f0 = As[kb + lc][r];
                float f1 = As[kb + lc][r + 8];
                float f2 = As[kb + lc + 4][r];
                float f3 = As[kb + lc + 4][r + 8];
                split_tf32(f0, ah[mf][0], al[mf][0]);
                split_tf32(f1, ah[mf][1], al[mf][1]);
                split_tf32(f2, ah[mf][2], al[mf][2]);
                split_tf32(f3, ah[mf][3], al[mf][3]);
            }
            uint32_t bh[4][2], bl[4][2];
#pragma unroll
            for (int nf = 0; nf < 4; nf++) {
                int n = wn + nf * 8 + lq;
                float f0 = Bs[kb + lc][n];
                float f1 = Bs[kb + lc + 4][n];
                split_tf32(f0, bh[nf][0], bl[nf][0]);
                split_tf32(f1, bh[nf][1], bl[nf][1]);
            }
#pragma unroll
            for (int mf = 0; mf < 2; mf++)
#pragma unroll
                for (int nf = 0; nf < 4; nf++) {
                    mma_tf32(c[mf][nf], ah[mf], bh[nf]);  // hi*hi
                    mma_tf32(c[mf][nf], ah[mf], bl[nf]);  // hi*lo
                    mma_tf32(c[mf][nf], al[mf], bh[nf]);  // lo*hi
                }
        }
        __syncthreads();
    }

#pragma unroll
    for (int mf = 0; mf < 2; mf++)
#pragma unroll
        for (int half = 0; half < 2; half++) {
            int row = m0 + wm + mf * 16 + lq + half * 8;
            int b = row / Tt;
            int t = row - b * Tt;
            size_t base = ((size_t)t * Bsz + b) * G3H + n0 + wn;
#pragma unroll
            for (int nf = 0; nf < 4; nf++) {
                int col = nf * 8 + lc * 2;
                float2 o;
                o.x = c[mf][nf][half * 2 + 0] + b_ih[n0 + wn + col];
                o.y = c[mf][nf][half * 2 + 1] + b_ih[n0 + wn + col + 1];
                *reinterpret_cast<float2*>(&g_xproj[base + col]) = o;
            }
        }
}

// ---------------- persistent GRU scan (vectorized) ----------------------------
template <int R>
__device__ void scan_body(float (*hs)[Hh], int start,
                          const float* __restrict__ b_hh,
                          const int* __restrict__ lengths) {
    const int j = threadIdx.x;

    int rows[R], lens[R];
#pragma unroll
    for (int i = 0; i < R; i++) {
        int p = start + i;
        rows[i] = (p < Bsz) ? g_order[p] : 0;
        lens[i] = (p < Bsz) ? lengths[rows[i]] : 0;
    }
#pragma unroll
    for (int i = 0; i < R; i++) hs[i][j] = 0.0f;
    __syncthreads();

    int maxlen = 0;
#pragma unroll
    for (int i = 0; i < R; i++) maxlen = max(maxlen, lens[i]);

    const float bhr = b_hh[j], bhz = b_hh[Hh + j], bhn = b_hh[2 * Hh + j];

    for (int t = 0; t < maxlen; t++) {
        float ar[R], az[R], an[R];
#pragma unroll
        for (int i = 0; i < R; i++) { ar[i] = 0.f; az[i] = 0.f; an[i] = 0.f; }

        for (int kq = 0; kq < Hh / 4; kq++) {
            float4 wr4 = g_wv4[(kq * 3 + 0) * Hh + j];
            float4 wz4 = g_wv4[(kq * 3 + 1) * Hh + j];
            float4 wn4 = g_wv4[(kq * 3 + 2) * Hh + j];
#pragma unroll
            for (int i = 0; i < R; i++) {
                float4 h4 = *reinterpret_cast<const float4*>(&hs[i][kq * 4]);
                ar[i] = fmaf(h4.x, wr4.x, ar[i]);
                ar[i] = fmaf(h4.y, wr4.y, ar[i]);
                ar[i] = fmaf(h4.z, wr4.z, ar[i]);
                ar[i] = fmaf(h4.w, wr4.w, ar[i]);
                az[i] = fmaf(h4.x, wz4.x, az[i]);
                az[i] = fmaf(h4.y, wz4.y, az[i]);
                az[i] = fmaf(h4.z, wz4.z, az[i]);
                az[i] = fmaf(h4.w, wz4.w, az[i]);
                an[i] = fmaf(h4.x, wn4.x, an[i]);
                an[i] = fmaf(h4.y, wn4.y, an[i]);
                an[i] = fmaf(h4.z, wn4.z, an[i]);
                an[i] = fmaf(h4.w, wn4.w, an[i]);
            }
        }

        float hnew[R];
#pragma unroll
        for (int i = 0; i < R; i++) {
            float hold = hs[i][j];
            if (t < lens[i]) {
                const float* xp = &g_xproj[((size_t)t * Bsz + rows[i]) * G3H + j];
                float r = 1.0f / (1.0f + expf(-(xp[0] + ar[i] + bhr)));
                float z = 1.0f / (1.0f + expf(-(xp[Hh] + az[i] + bhz)));
                float n = tanhf(xp[2 * Hh] + r * (an[i] + bhn));
                hnew[i] = (1.0f - z) * n + z * hold;
            } else {
                hnew[i] = hold;
            }
        }
        __syncthreads();
#pragma unroll
        for (int i = 0; i < R; i++) hs[i][j] = hnew[i];
        __syncthreads();
    }

#pragma unroll
    for (int i = 0; i < R; i++)
        if (start + i < Bsz)
            g_hA[(size_t)rows[i] * Hh + j] = hs[i][j];
}

__global__ void __launch_bounds__(256, 1) k_scan(const float* __restrict__ b_hh,
                                                 const int* __restrict__ lengths) {
    __shared__ float hs[16][Hh];
    int bb = blockIdx.x;
    if (bb < 48)        scan_body<4>(hs, 4 * bb, b_hh, lengths);
    else if (bb < 80)   scan_body<6>(hs, 192 + 6 * (bb - 48), b_hh, lengths);
    else if (bb < 108)  scan_body<8>(hs, 384 + 8 * (bb - 80), b_hh, lengths);
    else if (bb < 128)  scan_body<11>(hs, 608 + 11 * (bb - 108), b_hh, lengths);
    else                scan_body<16>(hs, 828 + 16 * (bb - 128), b_hh, lengths);
}

// ---------------- kmeans -----------------------------------------------------
__global__ void k_cinit(IdxList il) {
    int d = threadIdx.x;
#pragma unroll
    for (int k = 0; k < KK; k++)
        g_centers[k * Hh + d] = g_hA[(size_t)il.v[k] * Hh + d];
}

__global__ void k_assign() {
    __shared__ float cs[KK * Hh];
    int tid = threadIdx.x;  // 128
    for (int i = tid; i < KK * Hh; i += 128) cs[i] = g_centers[i];
    __syncthreads();

    int warp = tid >> 5, lane = tid & 31;
    int b = blockIdx.x * 4 + warp;

    float dist[KK];
#pragma unroll
    for (int k = 0; k < KK; k++) dist[k] = 0.0f;
#pragma unroll
    for (int i = 0; i < 8; i++) {
        int d = lane + i * 32;
        float v = g_hA[(size_t)b * Hh + d];
#pragma unroll
        for (int k = 0; k < KK; k++) {
            float df = v - cs[k * Hh + d];
            dist[k] += df * df;
        }
    }
#pragma unroll
    for (int k = 0; k < KK; k++)
#pragma unroll
        for (int o = 16; o > 0; o >>= 1)
            dist[k] += __shfl_xor_sync(0xffffffffu, dist[k], o);

    int code = 0;
    float best = dist[0];
#pragma unroll
    for (int k = 1; k < KK; k++)
        if (dist[k] < best) { best = dist[k]; code = k; }
    if (lane == 0) g_codes[b] = code;
}

__global__ void k_update() {
    __shared__ int codes[Bsz];
    int k = blockIdx.x, d = threadIdx.x;
    for (int i = d; i < Bsz; i += 256) codes[i] = g_codes[i];
    __syncthreads();
    float s = 0.0f, cnt = 0.0f;
    for (int b = 0; b < Bsz; b++) {
        if (codes[b] == k) { s += g_hA[(size_t)b * Hh + d]; cnt += 1.0f; }
    }
    float cold = g_centers[k * Hh + d];
    g_centers[k * Hh + d] = (cnt > 0.0f) ? (s / fmaxf(cnt, 1.0f)) : cold;
}

// ---------------- GCN (adj = I -> per-center MLP) ----------------------------
__global__ void k_hprime(const float* __restrict__ g1w, const float* __restrict__ g1b,
                         const float* __restrict__ g2w, const float* __restrict__ g2b) {
    int k = blockIdx.x, j = threadIdx.x;
    __shared__ float c[Hh], tmp[Hh];
    c[j] = g_centers[k * Hh + j];
    __syncthreads();
    float s = g1b[j];
    for (int d = 0; d < Hh; d++) s += c[d] * g1w[(size_t)d * Hh + j];
    tmp[j] = fmaxf(s, 0.0f);
    __syncthreads();
    float s2 = g2b[j];
    for (int d = 0; d < Hh; d++) s2 += tmp[d] * g2w[(size_t)d * Hh + j];
    g_hprime[k * Hh + j] = fmaxf(s2, 0.0f);
}

// ---------------- epilogue ---------------------------------------------------
__global__ void k_epi(const float* __restrict__ wt1w, const float* __restrict__ wt1b,
                      const float* __restrict__ wt2w, const float* __restrict__ wt2b,
                      float* __restrict__ out) {
    __shared__ float cs[KK * Hh], hp[KK * Hh], w1s[Hh], w2s[Hh];
    int tid = threadIdx.x;  // 128
    for (int i = tid; i < KK * Hh; i += 128) { cs[i] = g_centers[i]; hp[i] = g_hprime[i]; }
    for (int i = tid; i < Hh; i += 128)      { w1s[i] = wt1w[i]; w2s[i] = wt2w[i]; }
    __syncthreads();

    int warp = tid >> 5, lane = tid & 31;
    int b = blockIdx.x * 4 + warp;

    float e[KK];
#pragma unroll
    for (int k = 0; k < KK; k++) e[k] = 0.0f;
    float hv[8];
#pragma unroll
    for (int i = 0; i < 8; i++) {
        int d = lane + i * 32;
        float v = g_hA[(size_t)b * Hh + d];
        hv[i] = v;
#pragma unroll
        for (int k = 0; k < KK; k++) e[k] += v * cs[k * Hh + d];
    }
#pragma unroll
    for (int k = 0; k < KK; k++)
#pragma unroll
        for (int o = 16; o > 0; o >>= 1)
            e[k] += __shfl_xor_sync(0xffffffffu, e[k], o);

    float mx = 0.0f;
#pragma unroll
    for (int k = 0; k < KK; k++) { e[k] = fmaxf(e[k], 0.0f); mx = fmaxf(mx, e[k]); }
    float den = 0.0f, sc[KK];
#pragma unroll
    for (int k = 0; k < KK; k++) { sc[k] = expf(e[k] - mx); den += sc[k]; }
    float inv = 1.0f / den;
#pragma unroll
    for (int k = 0; k < KK; k++) sc[k] *= inv;

    float w1p = 0.0f, w2p = 0.0f, cl[8];
#pragma unroll
    for (int i = 0; i < 8; i++) {
        int d = lane + i * 32;
        float s = 0.0f;
#pragma unroll
        for (int k = 0; k < KK; k++) s += sc[k] * hp[k * Hh + d];
        cl[i] = s;
        w1p += s * w1s[d];
        w2p += hv[i] * w2s[d];
    }
#pragma unroll
    for (int o = 16; o > 0; o >>= 1) {
        w1p += __shfl_xor_sync(0xffffffffu, w1p, o);
        w2p += __shfl_xor_sync(0xffffffffu, w2p, o);
    }
    float w1 = 1.0f / (1.0f + expf(-(w1p + wt1b[0])));
    float w2 = 1.0f / (1.0f + expf(-(w2p + wt2b[0])));
    float w1n = w1 / (w1 + w2 + 1e-8f);
#pragma unroll
    for (int i = 0; i < 8; i++) {
        int d = lane + i * 32;
        out[(size_t)b * Hh + d] = w1n * cl[i] + (1.0f - w1n) * hv[i];
    }
}

// ---------------- host: JAX threefry replication -----------------------------
static inline uint32_t rotl32(uint32_t v, int d) { return (v << d) | (v >> (32 - d)); }

static void threefry2x32(uint32_t k0, uint32_t k1, uint32_t c0, uint32_t c1,
                         uint32_t* o0, uint32_t* o1) {
    uint32_t ks0 = k0, ks1 = k1, ks2 = k0 ^ k1 ^ 0x1BD11BDAu;
    uint32_t x0 = c0 + ks0, x1 = c1 + ks1;
    const int rA[4] = {13, 15, 26, 6};
    const int rB[4] = {17, 29, 16, 24};
#define TF4(R) for (int i_ = 0; i_ < 4; i_++) { x0 += x1; x1 = rotl32(x1, R[i_]); x1 ^= x0; }
    TF4(rA); x0 += ks1; x1 += ks2 + 1u;
    TF4(rB); x0 += ks2; x1 += ks0 + 2u;
    TF4(rA); x0 += ks0; x1 += ks1 + 3u;
    TF4(rB); x0 += ks1; x1 += ks2 + 4u;
    TF4(rA); x0 += ks2; x1 += ks0 + 5u;
#undef TF4
    *o0 = x0; *o1 = x1;
}

static void compute_init_indices(int* out12) {
    uint32_t sk0, sk1;
    threefry2x32(0u, 42u, 0u, 1u, &sk0, &sk1);
    uint32_t keys[Bsz];
    for (int i = 0; i < Bsz; i++) {
        uint32_t o0, o1;
        threefry2x32(sk0, sk1, 0u, (uint32_t)i, &o0, &o1);
        keys[i] = o0 ^ o1;
    }
    int idx[Bsz];
    for (int i = 0; i < Bsz; i++) idx[i] = i;
    std::stable_sort(idx, idx + Bsz,
                     [&](int a, int b) { return keys[a] < keys[b]; });
    for (int k = 0; k < KK; k++) out12[k] = idx[k];
}

// ---------------- launch -----------------------------------------------------
extern "C" void kernel_launch(void* const* d_in, const int* in_sizes, int n_in,
                              void* d_out, int out_size) {
    const float* x       = (const float*)d_in[0];
    const int*   lengths = (const int*)  d_in[1];
    const float* w_ih    = (const float*)d_in[2];
    const float* w_hh    = (const float*)d_in[3];
    const float* b_ih    = (const float*)d_in[4];
    const float* b_hh    = (const float*)d_in[5];
    const float* g1w     = (const float*)d_in[6];
    const float* g1b     = (const float*)d_in[7];
    const float* g2w     = (const float*)d_in[8];
    const float* g2b     = (const float*)d_in[9];
    const float* wt1w    = (const float*)d_in[10];
    const float* wt1b    = (const float*)d_in[11];
    const float* wt2w    = (const float*)d_in[12];
    const float* wt2b    = (const float*)d_in[13];
    float* out = (float*)d_out;
    (void)in_sizes; (void)n_in; (void)out_size;

    IdxList il;
    compute_init_indices(il.v);

    k_init<<<1024, 256>>>();
    k_trans<<<(G3H * Hh + 255) / 256, 256>>>(w_hh);
    k_sort<<<1, 256>>>(lengths);
    k_xproj<<<dim3(12, 1600), 256>>>(x, w_ih, b_ih, lengths);
    k_scan<<<NSCAN, 256>>>(b_hh, lengths);
    k_cinit<<<1, 256>>>(il);
    for (int it = 0; it < KMI; it++) {
        k_assign<<<256, 128>>>();
        k_update<<<KK, 256>>>();
    }
    k_hprime<<<KK, 256>>>(g1w, g1b, g2w, g2b);
    k_epi<<<256, 128>>>(wt1w, wt1b, wt2w, wt2b, out);
}

// round 9
// speedup vs baseline: 1.1263x; 1.0193x over previous
#include <cuda_runtime.h>
#include <stdint.h>
#include <math.h>
#include <algorithm>

#define Bsz 1024
#define Tt  200
#define Dd  512
#define Hh  256
#define KK  12
#define KMI 30
#define G3H 768
#define NSCAN 141

// ---------------- scratch ----------------------------------------------------
__device__ float g_xproj[(size_t)Tt * Bsz * G3H];  // [T][B][3H]
// packed recurrence weights: g_wv4[(kq*3+g)*Hh + j] = w_hh[g*256+j][4kq..4kq+3]
__device__ float4 g_wv4[(Hh / 4) * 3 * Hh];
__device__ float g_hA[Bsz * Hh];
__device__ float g_centers[KK * Hh];
__device__ float g_hprime[KK * Hh];
__device__ int   g_codes[Bsz];
__device__ int   g_order[Bsz];    // row indices sorted by length desc

struct IdxList { int v[KK]; };

__global__ void k_init() {
    int idx = blockIdx.x * blockDim.x + threadIdx.x;
    if (idx < Bsz * Hh) g_hA[idx] = 0.0f;
}

// ---------------- repack w_hh: [3H][H] -> float4-blocked ---------------------
__global__ void k_trans(const float* __restrict__ w_hh) {
    int idx = blockIdx.x * 256 + threadIdx.x;
    if (idx < G3H * Hh) {
        int n = idx / Hh, k = idx - n * Hh;  // w_hh[n][k]
        int g = n >> 8, j = n & 255;
        int kq = k >> 2, kr = k & 3;
        reinterpret_cast<float*>(g_wv4)[(size_t)(((kq * 3) + g) * Hh + j) * 4 + kr] =
            w_hh[idx];
    }
}

// ---------------- rank-sort rows by length desc -------------------------------
__global__ void k_sort(const int* __restrict__ lengths) {
    __shared__ int ls[Bsz];
    int tid = threadIdx.x;
    for (int i = tid; i < Bsz; i += 256) ls[i] = lengths[i];
    __syncthreads();
    for (int i = tid; i < Bsz; i += 256) {
        int li = ls[i];
        int r = 0;
        for (int b = 0; b < Bsz; b++) {
            int lb = ls[b];
            r += (lb > li) || (lb == li && b < i);
        }
        g_order[r] = i;
    }
}

// ---------------- tf32 helpers ------------------------------------------------
__device__ __forceinline__ uint32_t f2tf32(float f) {
    uint32_t r;
    asm("cvt.rna.tf32.f32 %0, %1;" : "=r"(r) : "f"(f));
    return r;
}
__device__ __forceinline__ void split_tf32(float f, uint32_t& hi, uint32_t& lo) {
    hi = f2tf32(f);
    lo = f2tf32(f - __uint_as_float(hi));
}
__device__ __forceinline__ void mma_tf32(float* c, const uint32_t* a,
                                         const uint32_t* b) {
    asm volatile(
        "mma.sync.aligned.m16n8k8.row.col.f32.tf32.tf32.f32 "
        "{%0,%1,%2,%3}, {%4,%5,%6,%7}, {%8,%9}, {%0,%1,%2,%3};"
        : "+f"(c[0]), "+f"(c[1]), "+f"(c[2]), "+f"(c[3])
        : "r"(a[0]), "r"(a[1]), "r"(a[2]), "r"(a[3]), "r"(b[0]), "r"(b[1]));
}

// ---------------- x-projection GEMM (tensor cores, 3xTF32, double-buffered) --
__global__ void __launch_bounds__(256, 3) k_xproj(const float* __restrict__ x,
                                                  const float* __restrict__ w_ih,
                                                  const float* __restrict__ b_ih,
                                                  const int* __restrict__ lengths) {
    const int m0 = blockIdx.y * 128;
    const int n0 = blockIdx.x * 64;

    {   // skip block if no covered (b,t) is ever consumed
        int b_first = m0 / Tt, b_last = (m0 + 127) / Tt;
        bool need = false;
        for (int b = b_first; b <= b_last && b < Bsz; b++) {
            int t_start = (m0 > b * Tt) ? (m0 - b * Tt) : 0;
            if (lengths[b] > t_start) need = true;
        }
        if (!need) return;
    }

    __shared__ float As[2][16][132];   // fp32, split to tf32 in registers
    __shared__ float Bs[2][16][68];

    const int tid = threadIdx.x;
    const int lr = tid >> 2, lc4 = tid & 3;
    const int wid = tid >> 5, lane = tid & 31;
    const int wm = (wid & 3) * 32;
    const int wn = (wid >> 2) * 32;
    const int lq = lane >> 2, lc = lane & 3;

    float c[2][4][4];
#pragma unroll
    for (int mf = 0; mf < 2; mf++)
#pragma unroll
        for (int nf = 0; nf < 4; nf++)
#pragma unroll
            for (int q = 0; q < 4; q++) c[mf][nf][q] = 0.0f;

    // stage k0=0 into buffer 0
    {
        float4 v0 = *reinterpret_cast<const float4*>(
            &x[(size_t)(m0 + lr) * Dd + lc4 * 4]);
        float4 v1 = *reinterpret_cast<const float4*>(
            &x[(size_t)(m0 + lr + 64) * Dd + lc4 * 4]);
        float4 vb = *reinterpret_cast<const float4*>(
            &w_ih[(size_t)(n0 + lr) * Dd + lc4 * 4]);
        As[0][lc4 * 4 + 0][lr] = v0.x; As[0][lc4 * 4 + 1][lr] = v0.y;
        As[0][lc4 * 4 + 2][lr] = v0.z; As[0][lc4 * 4 + 3][lr] = v0.w;
        As[0][lc4 * 4 + 0][lr + 64] = v1.x; As[0][lc4 * 4 + 1][lr + 64] = v1.y;
        As[0][lc4 * 4 + 2][lr + 64] = v1.z; As[0][lc4 * 4 + 3][lr + 64] = v1.w;
        Bs[0][lc4 * 4 + 0][lr] = vb.x; Bs[0][lc4 * 4 + 1][lr] = vb.y;
        Bs[0][lc4 * 4 + 2][lr] = vb.z; Bs[0][lc4 * 4 + 3][lr] = vb.w;
    }
    __syncthreads();

    int buf = 0;
    for (int k0 = 0; k0 < Dd; k0 += 16) {
        const bool has_next = (k0 + 16 < Dd);
        float4 pa0, pa1, pb;
        if (has_next) {
            pa0 = *reinterpret_cast<const float4*>(
                &x[(size_t)(m0 + lr) * Dd + k0 + 16 + lc4 * 4]);
            pa1 = *reinterpret_cast<const float4*>(
                &x[(size_t)(m0 + lr + 64) * Dd + k0 + 16 + lc4 * 4]);
            pb = *reinterpret_cast<const float4*>(
                &w_ih[(size_t)(n0 + lr) * Dd + k0 + 16 + lc4 * 4]);
        }

#pragma unroll
        for (int ks = 0; ks < 2; ks++) {
            const int kb = ks * 8;
            uint32_t ah[2][4], al[2][4];
#pragma unroll
            for (int mf = 0; mf < 2; mf++) {
                int r = wm + mf * 16 + lq;
                float f0 = As[buf][kb + lc][r];
                float f1 = As[buf][kb + lc][r + 8];
                float f2 = As[buf][kb + lc + 4][r];
                float f3 = As[buf][kb + lc + 4][r + 8];
                split_tf32(f0, ah[mf][0], al[mf][0]);
                split_tf32(f1, ah[mf][1], al[mf][1]);
                split_tf32(f2, ah[mf][2], al[mf][2]);
                split_tf32(f3, ah[mf][3], al[mf][3]);
            }
            uint32_t bh[4][2], bl[4][2];
#pragma unroll
            for (int nf = 0; nf < 4; nf++) {
                int n = wn + nf * 8 + lq;
                float f0 = Bs[buf][kb + lc][n];
                float f1 = Bs[buf][kb + lc + 4][n];
                split_tf32(f0, bh[nf][0], bl[nf][0]);
                split_tf32(f1, bh[nf][1], bl[nf][1]);
            }
#pragma unroll
            for (int mf = 0; mf < 2; mf++)
#pragma unroll
                for (int nf = 0; nf < 4; nf++) {
                    mma_tf32(c[mf][nf], ah[mf], bh[nf]);  // hi*hi
                    mma_tf32(c[mf][nf], ah[mf], bl[nf]);  // hi*lo
                    mma_tf32(c[mf][nf], al[mf], bh[nf]);  // lo*hi
                }
        }

        if (has_next) {
            int nb = buf ^ 1;
            As[nb][lc4 * 4 + 0][lr] = pa0.x; As[nb][lc4 * 4 + 1][lr] = pa0.y;
            As[nb][lc4 * 4 + 2][lr] = pa0.z; As[nb][lc4 * 4 + 3][lr] = pa0.w;
            As[nb][lc4 * 4 + 0][lr + 64] = pa1.x; As[nb][lc4 * 4 + 1][lr + 64] = pa1.y;
            As[nb][lc4 * 4 + 2][lr + 64] = pa1.z; As[nb][lc4 * 4 + 3][lr + 64] = pa1.w;
            Bs[nb][lc4 * 4 + 0][lr] = pb.x; Bs[nb][lc4 * 4 + 1][lr] = pb.y;
            Bs[nb][lc4 * 4 + 2][lr] = pb.z; Bs[nb][lc4 * 4 + 3][lr] = pb.w;
            __syncthreads();
            buf = nb;
        }
    }

#pragma unroll
    for (int mf = 0; mf < 2; mf++)
#pragma unroll
        for (int half = 0; half < 2; half++) {
            int row = m0 + wm + mf * 16 + lq + half * 8;
            int b = row / Tt;
            int t = row - b * Tt;
            size_t base = ((size_t)t * Bsz + b) * G3H + n0 + wn;
#pragma unroll
            for (int nf = 0; nf < 4; nf++) {
                int col = nf * 8 + lc * 2;
                float2 o;
                o.x = c[mf][nf][half * 2 + 0] + b_ih[n0 + wn + col];
                o.y = c[mf][nf][half * 2 + 1] + b_ih[n0 + wn + col + 1];
                *reinterpret_cast<float2*>(&g_xproj[base + col]) = o;
            }
        }
}

// ---------------- persistent GRU scan (vectorized) ----------------------------
template <int R>
__device__ void scan_body(float (*hs)[Hh], int start,
                          const float* __restrict__ b_hh,
                          const int* __restrict__ lengths) {
    const int j = threadIdx.x;

    int rows[R], lens[R];
#pragma unroll
    for (int i = 0; i < R; i++) {
        int p = start + i;
        rows[i] = (p < Bsz) ? g_order[p] : 0;
        lens[i] = (p < Bsz) ? lengths[rows[i]] : 0;
    }
#pragma unroll
    for (int i = 0; i < R; i++) hs[i][j] = 0.0f;
    __syncthreads();

    int maxlen = 0;
#pragma unroll
    for (int i = 0; i < R; i++) maxlen = max(maxlen, lens[i]);

    const float bhr = b_hh[j], bhz = b_hh[Hh + j], bhn = b_hh[2 * Hh + j];

    for (int t = 0; t < maxlen; t++) {
        float ar[R], az[R], an[R];
#pragma unroll
        for (int i = 0; i < R; i++) { ar[i] = 0.f; az[i] = 0.f; an[i] = 0.f; }

        for (int kq = 0; kq < Hh / 4; kq++) {
            float4 wr4 = g_wv4[(kq * 3 + 0) * Hh + j];
            float4 wz4 = g_wv4[(kq * 3 + 1) * Hh + j];
            float4 wn4 = g_wv4[(kq * 3 + 2) * Hh + j];
#pragma unroll
            for (int i = 0; i < R; i++) {
                float4 h4 = *reinterpret_cast<const float4*>(&hs[i][kq * 4]);
                ar[i] = fmaf(h4.x, wr4.x, ar[i]);
                ar[i] = fmaf(h4.y, wr4.y, ar[i]);
                ar[i] = fmaf(h4.z, wr4.z, ar[i]);
                ar[i] = fmaf(h4.w, wr4.w, ar[i]);
                az[i] = fmaf(h4.x, wz4.x, az[i]);
                az[i] = fmaf(h4.y, wz4.y, az[i]);
                az[i] = fmaf(h4.z, wz4.z, az[i]);
                az[i] = fmaf(h4.w, wz4.w, az[i]);
                an[i] = fmaf(h4.x, wn4.x, an[i]);
                an[i] = fmaf(h4.y, wn4.y, an[i]);
                an[i] = fmaf(h4.z, wn4.z, an[i]);
                an[i] = fmaf(h4.w, wn4.w, an[i]);
            }
        }

        float hnew[R];
#pragma unroll
        for (int i = 0; i < R; i++) {
            float hold = hs[i][j];
            if (t < lens[i]) {
                const float* xp = &g_xproj[((size_t)t * Bsz + rows[i]) * G3H + j];
                float r = 1.0f / (1.0f + expf(-(xp[0] + ar[i] + bhr)));
                float z = 1.0f / (1.0f + expf(-(xp[Hh] + az[i] + bhz)));
                float n = tanhf(xp[2 * Hh] + r * (an[i] + bhn));
                hnew[i] = (1.0f - z) * n + z * hold;
            } else {
                hnew[i] = hold;
            }
        }
        __syncthreads();
#pragma unroll
        for (int i = 0; i < R; i++) hs[i][j] = hnew[i];
        __syncthreads();
    }

#pragma unroll
    for (int i = 0; i < R; i++)
        if (start + i < Bsz)
            g_hA[(size_t)rows[i] * Hh + j] = hs[i][j];
}

__global__ void __launch_bounds__(256, 1) k_scan(const float* __restrict__ b_hh,
                                                 const int* __restrict__ lengths) {
    __shared__ float hs[16][Hh];
    int bb = blockIdx.x;
    if (bb < 48)        scan_body<4>(hs, 4 * bb, b_hh, lengths);
    else if (bb < 80)   scan_body<6>(hs, 192 + 6 * (bb - 48), b_hh, lengths);
    else if (bb < 108)  scan_body<8>(hs, 384 + 8 * (bb - 80), b_hh, lengths);
    else if (bb < 128)  scan_body<11>(hs, 608 + 11 * (bb - 108), b_hh, lengths);
    else                scan_body<16>(hs, 828 + 16 * (bb - 128), b_hh, lengths);
}

// ---------------- kmeans -----------------------------------------------------
__global__ void k_cinit(IdxList il) {
    int d = threadIdx.x;
#pragma unroll
    for (int k = 0; k < KK; k++)
        g_centers[k * Hh + d] = g_hA[(size_t)il.v[k] * Hh + d];
}

__global__ void k_assign() {
    __shared__ float cs[KK * Hh];
    int tid = threadIdx.x;  // 128
    for (int i = tid; i < KK * Hh; i += 128) cs[i] = g_centers[i];
    __syncthreads();

    int warp = tid >> 5, lane = tid & 31;
    int b = blockIdx.x * 4 + warp;

    float dist[KK];
#pragma unroll
    for (int k = 0; k < KK; k++) dist[k] = 0.0f;
#pragma unroll
    for (int i = 0; i < 8; i++) {
        int d = lane + i * 32;
        float v = g_hA[(size_t)b * Hh + d];
#pragma unroll
        for (int k = 0; k < KK; k++) {
            float df = v - cs[k * Hh + d];
            dist[k] += df * df;
        }
    }
#pragma unroll
    for (int k = 0; k < KK; k++)
#pragma unroll
        for (int o = 16; o > 0; o >>= 1)
            dist[k] += __shfl_xor_sync(0xffffffffu, dist[k], o);

    int code = 0;
    float best = dist[0];
#pragma unroll
    for (int k = 1; k < KK; k++)
        if (dist[k] < best) { best = dist[k]; code = k; }
    if (lane == 0) g_codes[b] = code;
}

// deterministic update: warp 0 builds ascending member list via ballot,
// then 256 threads (one per d) sum only matching rows.
__global__ void k_update() {
    __shared__ int list[Bsz];
    __shared__ int cnt_s;
    const int k = blockIdx.x, tid = threadIdx.x;

    if (tid < 32) {
        int cnt = 0;
        for (int base = 0; base < Bsz; base += 32) {
            int code = g_codes[base + tid];
            unsigned m = __ballot_sync(0xffffffffu, code == k);
            int pos = cnt + __popc(m & ((1u << tid) - 1u));
            if (code == k) list[pos] = base + tid;
            cnt += __popc(m);
        }
        if (tid == 0) cnt_s = cnt;
    }
    __syncthreads();

    const int cnt = cnt_s;
    const int d = tid;
    float s = 0.0f;
#pragma unroll 4
    for (int i = 0; i < cnt; i++)
        s += g_hA[(size_t)list[i] * Hh + d];
    float cold = g_centers[k * Hh + d];
    g_centers[k * Hh + d] = (cnt > 0) ? (s / (float)cnt) : cold;
}

// ---------------- GCN (adj = I -> per-center MLP) ----------------------------
__global__ void k_hprime(const float* __restrict__ g1w, const float* __restrict__ g1b,
                         const float* __restrict__ g2w, const float* __restrict__ g2b) {
    int k = blockIdx.x, j = threadIdx.x;
    __shared__ float c[Hh], tmp[Hh];
    c[j] = g_centers[k * Hh + j];
    __syncthreads();
    float s = g1b[j];
    for (int d = 0; d < Hh; d++) s += c[d] * g1w[(size_t)d * Hh + j];
    tmp[j] = fmaxf(s, 0.0f);
    __syncthreads();
    float s2 = g2b[j];
    for (int d = 0; d < Hh; d++) s2 += tmp[d] * g2w[(size_t)d * Hh + j];
    g_hprime[k * Hh + j] = fmaxf(s2, 0.0f);
}

// ---------------- epilogue ---------------------------------------------------
__global__ void k_epi(const float* __restrict__ wt1w, const float* __restrict__ wt1b,
                      const float* __restrict__ wt2w, const float* __restrict__ wt2b,
                      float* __restrict__ out) {
    __shared__ float cs[KK * Hh], hp[KK * Hh], w1s[Hh], w2s[Hh];
    int tid = threadIdx.x;  // 128
    for (int i = tid; i < KK * Hh; i += 128) { cs[i] = g_centers[i]; hp[i] = g_hprime[i]; }
    for (int i = tid; i < Hh; i += 128)      { w1s[i] = wt1w[i]; w2s[i] = wt2w[i]; }
    __syncthreads();

    int warp = tid >> 5, lane = tid & 31;
    int b = blockIdx.x * 4 + warp;

    float e[KK];
#pragma unroll
    for (int k = 0; k < KK; k++) e[k] = 0.0f;
    float hv[8];
#pragma unroll
    for (int i = 0; i < 8; i++) {
        int d = lane + i * 32;
        float v = g_hA[(size_t)b * Hh + d];
        hv[i] = v;
#pragma unroll
        for (int k = 0; k < KK; k++) e[k] += v * cs[k * Hh + d];
    }
#pragma unroll
    for (int k = 0; k < KK; k++)
#pragma unroll
        for (int o = 16; o > 0; o >>= 1)
            e[k] += __shfl_xor_sync(0xffffffffu, e[k], o);

    float mx = 0.0f;
#pragma unroll
    for (int k = 0; k < KK; k++) { e[k] = fmaxf(e[k], 0.0f); mx = fmaxf(mx, e[k]); }
    float den = 0.0f, sc[KK];
#pragma unroll
    for (int k = 0; k < KK; k++) { sc[k] = expf(e[k] - mx); den += sc[k]; }
    float inv = 1.0f / den;
#pragma unroll
    for (int k = 0; k < KK; k++) sc[k] *= inv;

    float w1p = 0.0f, w2p = 0.0f, cl[8];
#pragma unroll
    for (int i = 0; i < 8; i++) {
        int d = lane + i * 32;
        float s = 0.0f;
#pragma unroll
        for (int k = 0; k < KK; k++) s += sc[k] * hp[k * Hh + d];
        cl[i] = s;
        w1p += s * w1s[d];
        w2p += hv[i] * w2s[d];
    }
#pragma unroll
    for (int o = 16; o > 0; o >>= 1) {
        w1p += __shfl_xor_sync(0xffffffffu, w1p, o);
        w2p += __shfl_xor_sync(0xffffffffu, w2p, o);
    }
    float w1 = 1.0f / (1.0f + expf(-(w1p + wt1b[0])));
    float w2 = 1.0f / (1.0f + expf(-(w2p + wt2b[0])));
    float w1n = w1 / (w1 + w2 + 1e-8f);
#pragma unroll
    for (int i = 0; i < 8; i++) {
        int d = lane + i * 32;
        out[(size_t)b * Hh + d] = w1n * cl[i] + (1.0f - w1n) * hv[i];
    }
}

// ---------------- host: JAX threefry replication -----------------------------
static inline uint32_t rotl32(uint32_t v, int d) { return (v << d) | (v >> (32 - d)); }

static void threefry2x32(uint32_t k0, uint32_t k1, uint32_t c0, uint32_t c1,
                         uint32_t* o0, uint32_t* o1) {
    uint32_t ks0 = k0, ks1 = k1, ks2 = k0 ^ k1 ^ 0x1BD11BDAu;
    uint32_t x0 = c0 + ks0, x1 = c1 + ks1;
    const int rA[4] = {13, 15, 26, 6};
    const int rB[4] = {17, 29, 16, 24};
#define TF4(R) for (int i_ = 0; i_ < 4; i_++) { x0 += x1; x1 = rotl32(x1, R[i_]); x1 ^= x0; }
    TF4(rA); x0 += ks1; x1 += ks2 + 1u;
    TF4(rB); x0 += ks2; x1 += ks0 + 2u;
    TF4(rA); x0 += ks0; x1 += ks1 + 3u;
    TF4(rB); x0 += ks1; x1 += ks2 + 4u;
    TF4(rA); x0 += ks2; x1 += ks0 + 5u;
#undef TF4
    *o0 = x0; *o1 = x1;
}

static void compute_init_indices(int* out12) {
    uint32_t sk0, sk1;
    threefry2x32(0u, 42u, 0u, 1u, &sk0, &sk1);
    uint32_t keys[Bsz];
    for (int i = 0; i < Bsz; i++) {
        uint32_t o0, o1;
        threefry2x32(sk0, sk1, 0u, (uint32_t)i, &o0, &o1);
        keys[i] = o0 ^ o1;
    }
    int idx[Bsz];
    for (int i = 0; i < Bsz; i++) idx[i] = i;
    std::stable_sort(idx, idx + Bsz,
                     [&](int a, int b) { return keys[a] < keys[b]; });
    for (int k = 0; k < KK; k++) out12[k] = idx[k];
}

// ---------------- launch -----------------------------------------------------
extern "C" void kernel_launch(void* const* d_in, const int* in_sizes, int n_in,
                              void* d_out, int out_size) {
    const float* x       = (const float*)d_in[0];
    const int*   lengths = (const int*)  d_in[1];
    const float* w_ih    = (const float*)d_in[2];
    const float* w_hh    = (const float*)d_in[3];
    const float* b_ih    = (const float*)d_in[4];
    const float* b_hh    = (const float*)d_in[5];
    const float* g1w     = (const float*)d_in[6];
    const float* g1b     = (const float*)d_in[7];
    const float* g2w     = (const float*)d_in[8];
    const float* g2b     = (const float*)d_in[9];
    const float* wt1w    = (const float*)d_in[10];
    const float* wt1b    = (const float*)d_in[11];
    const float* wt2w    = (const float*)d_in[12];
    const float* wt2b    = (const float*)d_in[13];
    float* out = (float*)d_out;
    (void)in_sizes; (void)n_in; (void)out_size;

    IdxList il;
    compute_init_indices(il.v);

    k_init<<<1024, 256>>>();
    k_trans<<<(G3H * Hh + 255) / 256, 256>>>(w_hh);
    k_sort<<<1, 256>>>(lengths);
    k_xproj<<<dim3(12, 1600), 256>>>(x, w_ih, b_ih, lengths);
    k_scan<<<NSCAN, 256>>>(b_hh, lengths);
    k_cinit<<<1, 256>>>(il);
    for (int it = 0; it < KMI; it++) {
        k_assign<<<256, 128>>>();
        k_update<<<KK, 256>>>();
    }
    k_hprime<<<KK, 256>>>(g1w, g1b, g2w, g2b);
    k_epi<<<256, 128>>>(wt1w, wt1b, wt2w, wt2b, out);
}

// round 10
// speedup vs baseline: 1.3058x; 1.1594x over previous
#include <cuda_runtime.h>
#include <stdint.h>
#include <math.h>
#include <algorithm>

#define Bsz 1024
#define Tt  200
#define Dd  512
#define Hh  256
#define KK  12
#define KMI 30
#define G3H 768
#define NSCAN 141

// ---------------- scratch ----------------------------------------------------
__device__ float g_xproj[(size_t)Tt * Bsz * G3H];  // [T][B][3H]
// packed recurrence weights: g_wv4[(kq*3+g)*Hh + j] = w_hh[g*256+j][4kq..4kq+3]
__device__ float4 g_wv4[(Hh / 4) * 3 * Hh];
__device__ float g_hA[Bsz * Hh];
__device__ float g_centers[KK * Hh];
__device__ float g_hprime[KK * Hh];
__device__ int   g_codes[Bsz];
__device__ int   g_order[Bsz];    // row indices sorted by length desc

struct IdxList { int v[KK]; };

__global__ void k_init() {
    int idx = blockIdx.x * blockDim.x + threadIdx.x;
    if (idx < Bsz * Hh) g_hA[idx] = 0.0f;
}

// ---------------- repack w_hh: [3H][H] -> float4-blocked ---------------------
__global__ void k_trans(const float* __restrict__ w_hh) {
    int idx = blockIdx.x * 256 + threadIdx.x;
    if (idx < G3H * Hh) {
        int n = idx / Hh, k = idx - n * Hh;  // w_hh[n][k]
        int g = n >> 8, j = n & 255;
        int kq = k >> 2, kr = k & 3;
        reinterpret_cast<float*>(g_wv4)[(size_t)(((kq * 3) + g) * Hh + j) * 4 + kr] =
            w_hh[idx];
    }
}

// ---------------- rank-sort rows by length desc -------------------------------
__global__ void k_sort(const int* __restrict__ lengths) {
    __shared__ int ls[Bsz];
    int tid = threadIdx.x;
    for (int i = tid; i < Bsz; i += 256) ls[i] = lengths[i];
    __syncthreads();
    for (int i = tid; i < Bsz; i += 256) {
        int li = ls[i];
        int r = 0;
        for (int b = 0; b < Bsz; b++) {
            int lb = ls[b];
            r += (lb > li) || (lb == li && b < i);
        }
        g_order[r] = i;
    }
}

// ---------------- tf32 helpers ------------------------------------------------
__device__ __forceinline__ uint32_t f2tf32(float f) {
    uint32_t r;
    asm("cvt.rna.tf32.f32 %0, %1;" : "=r"(r) : "f"(f));
    return r;
}
__device__ __forceinline__ void split_tf32(float f, uint32_t& hi, uint32_t& lo) {
    hi = f2tf32(f);
    lo = f2tf32(f - __uint_as_float(hi));
}
__device__ __forceinline__ void mma_tf32(float* c, const uint32_t* a,
                                         const uint32_t* b) {
    asm volatile(
        "mma.sync.aligned.m16n8k8.row.col.f32.tf32.tf32.f32 "
        "{%0,%1,%2,%3}, {%4,%5,%6,%7}, {%8,%9}, {%0,%1,%2,%3};"
        : "+f"(c[0]), "+f"(c[1]), "+f"(c[2]), "+f"(c[3])
        : "r"(a[0]), "r"(a[1]), "r"(a[2]), "r"(a[3]), "r"(b[0]), "r"(b[1]));
}

// ---------------- packed f32x2 helpers (Blackwell FFMA2) ---------------------
typedef unsigned long long u64;
__device__ __forceinline__ u64 pack2(float lo, float hi) {
    u64 r;
    asm("mov.b64 %0, {%1, %2};" : "=l"(r) : "f"(lo), "f"(hi));
    return r;
}
__device__ __forceinline__ void fma2(u64& acc, u64 a, u64 b) {
    asm("fma.rn.f32x2 %0, %1, %2, %3;" : "=l"(acc) : "l"(a), "l"(b), "l"(acc));
}
__device__ __forceinline__ void unpack2(u64 v, float& lo, float& hi) {
    asm("mov.b64 {%0, %1}, %2;" : "=f"(lo), "=f"(hi) : "l"(v));
}

// ---------------- x-projection GEMM (tensor cores, 3xTF32, double-buffered) --
__global__ void __launch_bounds__(256, 3) k_xproj(const float* __restrict__ x,
                                                  const float* __restrict__ w_ih,
                                                  const float* __restrict__ b_ih,
                                                  const int* __restrict__ lengths) {
    const int m0 = blockIdx.y * 128;
    const int n0 = blockIdx.x * 64;

    {   // skip block if no covered (b,t) is ever consumed
        int b_first = m0 / Tt, b_last = (m0 + 127) / Tt;
        bool need = false;
        for (int b = b_first; b <= b_last && b < Bsz; b++) {
            int t_start = (m0 > b * Tt) ? (m0 - b * Tt) : 0;
            if (lengths[b] > t_start) need = true;
        }
        if (!need) return;
    }

    __shared__ float As[2][16][132];   // fp32, split to tf32 in registers
    __shared__ float Bs[2][16][68];

    const int tid = threadIdx.x;
    const int lr = tid >> 2, lc4 = tid & 3;
    const int wid = tid >> 5, lane = tid & 31;
    const int wm = (wid & 3) * 32;
    const int wn = (wid >> 2) * 32;
    const int lq = lane >> 2, lc = lane & 3;

    float c[2][4][4];
#pragma unroll
    for (int mf = 0; mf < 2; mf++)
#pragma unroll
        for (int nf = 0; nf < 4; nf++)
#pragma unroll
            for (int q = 0; q < 4; q++) c[mf][nf][q] = 0.0f;

    {
        float4 v0 = *reinterpret_cast<const float4*>(
            &x[(size_t)(m0 + lr) * Dd + lc4 * 4]);
        float4 v1 = *reinterpret_cast<const float4*>(
            &x[(size_t)(m0 + lr + 64) * Dd + lc4 * 4]);
        float4 vb = *reinterpret_cast<const float4*>(
            &w_ih[(size_t)(n0 + lr) * Dd + lc4 * 4]);
        As[0][lc4 * 4 + 0][lr] = v0.x; As[0][lc4 * 4 + 1][lr] = v0.y;
        As[0][lc4 * 4 + 2][lr] = v0.z; As[0][lc4 * 4 + 3][lr] = v0.w;
        As[0][lc4 * 4 + 0][lr + 64] = v1.x; As[0][lc4 * 4 + 1][lr + 64] = v1.y;
        As[0][lc4 * 4 + 2][lr + 64] = v1.z; As[0][lc4 * 4 + 3][lr + 64] = v1.w;
        Bs[0][lc4 * 4 + 0][lr] = vb.x; Bs[0][lc4 * 4 + 1][lr] = vb.y;
        Bs[0][lc4 * 4 + 2][lr] = vb.z; Bs[0][lc4 * 4 + 3][lr] = vb.w;
    }
    __syncthreads();

    int buf = 0;
    for (int k0 = 0; k0 < Dd; k0 += 16) {
        const bool has_next = (k0 + 16 < Dd);
        float4 pa0, pa1, pb;
        if (has_next) {
            pa0 = *reinterpret_cast<const float4*>(
                &x[(size_t)(m0 + lr) * Dd + k0 + 16 + lc4 * 4]);
            pa1 = *reinterpret_cast<const float4*>(
                &x[(size_t)(m0 + lr + 64) * Dd + k0 + 16 + lc4 * 4]);
            pb = *reinterpret_cast<const float4*>(
                &w_ih[(size_t)(n0 + lr) * Dd + k0 + 16 + lc4 * 4]);
        }

#pragma unroll
        for (int ks = 0; ks < 2; ks++) {
            const int kb = ks * 8;
            uint32_t ah[2][4], al[2][4];
#pragma unroll
            for (int mf = 0; mf < 2; mf++) {
                int r = wm + mf * 16 + lq;
                float f0 = As[buf][kb + lc][r];
                float f1 = As[buf][kb + lc][r + 8];
                float f2 = As[buf][kb + lc + 4][r];
                float f3 = As[buf][kb + lc + 4][r + 8];
                split_tf32(f0, ah[mf][0], al[mf][0]);
                split_tf32(f1, ah[mf][1], al[mf][1]);
                split_tf32(f2, ah[mf][2], al[mf][2]);
                split_tf32(f3, ah[mf][3], al[mf][3]);
            }
            uint32_t bh[4][2], bl[4][2];
#pragma unroll
            for (int nf = 0; nf < 4; nf++) {
                int n = wn + nf * 8 + lq;
                float f0 = Bs[buf][kb + lc][n];
                float f1 = Bs[buf][kb + lc + 4][n];
                split_tf32(f0, bh[nf][0], bl[nf][0]);
                split_tf32(f1, bh[nf][1], bl[nf][1]);
            }
#pragma unroll
            for (int mf = 0; mf < 2; mf++)
#pragma unroll
                for (int nf = 0; nf < 4; nf++) {
                    mma_tf32(c[mf][nf], ah[mf], bh[nf]);  // hi*hi
                    mma_tf32(c[mf][nf], ah[mf], bl[nf]);  // hi*lo
                    mma_tf32(c[mf][nf], al[mf], bh[nf]);  // lo*hi
                }
        }

        if (has_next) {
            int nb = buf ^ 1;
            As[nb][lc4 * 4 + 0][lr] = pa0.x; As[nb][lc4 * 4 + 1][lr] = pa0.y;
            As[nb][lc4 * 4 + 2][lr] = pa0.z; As[nb][lc4 * 4 + 3][lr] = pa0.w;
            As[nb][lc4 * 4 + 0][lr + 64] = pa1.x; As[nb][lc4 * 4 + 1][lr + 64] = pa1.y;
            As[nb][lc4 * 4 + 2][lr + 64] = pa1.z; As[nb][lc4 * 4 + 3][lr + 64] = pa1.w;
            Bs[nb][lc4 * 4 + 0][lr] = pb.x; Bs[nb][lc4 * 4 + 1][lr] = pb.y;
            Bs[nb][lc4 * 4 + 2][lr] = pb.z; Bs[nb][lc4 * 4 + 3][lr] = pb.w;
            __syncthreads();
            buf = nb;
        }
    }

#pragma unroll
    for (int mf = 0; mf < 2; mf++)
#pragma unroll
        for (int half = 0; half < 2; half++) {
            int row = m0 + wm + mf * 16 + lq + half * 8;
            int b = row / Tt;
            int t = row - b * Tt;
            size_t base = ((size_t)t * Bsz + b) * G3H + n0 + wn;
#pragma unroll
            for (int nf = 0; nf < 4; nf++) {
                int col = nf * 8 + lc * 2;
                float2 o;
                o.x = c[mf][nf][half * 2 + 0] + b_ih[n0 + wn + col];
                o.y = c[mf][nf][half * 2 + 1] + b_ih[n0 + wn + col + 1];
                *reinterpret_cast<float2*>(&g_xproj[base + col]) = o;
            }
        }
}

// ---------------- persistent GRU scan (FFMA2, transposed h state) ------------
// hs[k][row] layout, stride 18 floats: row-pairs are 8B-aligned (offset
// (18k+2p)*4 = 8*(9k+p)), broadcast reads, <=2-way write conflicts.
template <int R>
__device__ void scan_body(float (*hs)[18], int start,
                          const float* __restrict__ b_hh,
                          const int* __restrict__ lengths) {
    const int j = threadIdx.x;
    constexpr int P = R / 2;          // full row pairs
    constexpr bool ODD = (R & 1) != 0;

    int rows[R], lens[R];
#pragma unroll
    for (int i = 0; i < R; i++) {
        int p = start + i;
        rows[i] = (p < Bsz) ? g_order[p] : 0;
        lens[i] = (p < Bsz) ? lengths[rows[i]] : 0;
    }
#pragma unroll
    for (int i = 0; i < 18; i++) hs[j][i] = 0.0f;
    __syncthreads();

    int maxlen = 0;
#pragma unroll
    for (int i = 0; i < R; i++) maxlen = max(maxlen, lens[i]);

    const float bhr = b_hh[j], bhz = b_hh[Hh + j], bhn = b_hh[2 * Hh + j];

    for (int t = 0; t < maxlen; t++) {
        u64 ar2[P > 0 ? P : 1], az2[P > 0 ? P : 1], an2[P > 0 ? P : 1];
        float art = 0.f, azt = 0.f, ant = 0.f;  // odd tail row
#pragma unroll
        for (int p = 0; p < P; p++) {
            ar2[p] = pack2(0.f, 0.f);
            az2[p] = pack2(0.f, 0.f);
            an2[p] = pack2(0.f, 0.f);
        }

        for (int kq = 0; kq < Hh / 4; kq++) {
            float4 wr4 = g_wv4[(kq * 3 + 0) * Hh + j];
            float4 wz4 = g_wv4[(kq * 3 + 1) * Hh + j];
            float4 wn4 = g_wv4[(kq * 3 + 2) * Hh + j];
            float wra[4] = {wr4.x, wr4.y, wr4.z, wr4.w};
            float wza[4] = {wz4.x, wz4.y, wz4.z, wz4.w};
            float wna[4] = {wn4.x, wn4.y, wn4.z, wn4.w};
#pragma unroll
            for (int kk = 0; kk < 4; kk++) {
                const int k = kq * 4 + kk;
                u64 wrr = pack2(wra[kk], wra[kk]);
                u64 wzz = pack2(wza[kk], wza[kk]);
                u64 wnn = pack2(wna[kk], wna[kk]);
#pragma unroll
                for (int p = 0; p < P; p++) {
                    u64 h2 = *reinterpret_cast<const u64*>(&hs[k][2 * p]);
                    fma2(ar2[p], h2, wrr);
                    fma2(az2[p], h2, wzz);
                    fma2(an2[p], h2, wnn);
                }
                if (ODD) {
                    float h = hs[k][R - 1];
                    art = fmaf(h, wra[kk], art);
                    azt = fmaf(h, wza[kk], azt);
                    ant = fmaf(h, wna[kk], ant);
                }
            }
        }

        float ar[R], az[R], an[R];
#pragma unroll
        for (int p = 0; p < P; p++) {
            unpack2(ar2[p], ar[2 * p], ar[2 * p + 1]);
            unpack2(az2[p], az[2 * p], az[2 * p + 1]);
            unpack2(an2[p], an[2 * p], an[2 * p + 1]);
        }
        if (ODD) { ar[R - 1] = art; az[R - 1] = azt; an[R - 1] = ant; }

        float hnew[R];
#pragma unroll
        for (int i = 0; i < R; i++) {
            float hold = hs[j][i];
            if (t < lens[i]) {
                const float* xp = &g_xproj[((size_t)t * Bsz + rows[i]) * G3H + j];
                float r = 1.0f / (1.0f + expf(-(xp[0] + ar[i] + bhr)));
                float z = 1.0f / (1.0f + expf(-(xp[Hh] + az[i] + bhz)));
                float n = tanhf(xp[2 * Hh] + r * (an[i] + bhn));
                hnew[i] = (1.0f - z) * n + z * hold;
            } else {
                hnew[i] = hold;
            }
        }
        __syncthreads();
#pragma unroll
        for (int i = 0; i < R; i++) hs[j][i] = hnew[i];
        __syncthreads();
    }

#pragma unroll
    for (int i = 0; i < R; i++)
        if (start + i < Bsz)
            g_hA[(size_t)rows[i] * Hh + j] = hs[j][i];
}

// Static schedule over sorted ranks (uniform-length order statistics):
//   bb   0..47 : R=4,  start = 4*bb           (rows    0..191)
//   bb  48..79 : R=6,  start = 192+6*(bb-48)  (rows  192..383)
//   bb  80..107: R=8,  start = 384+8*(bb-80)  (rows  384..607)
//   bb 108..127: R=11, start = 608+11*(bb-108)(rows  608..827)
//   bb 128..140: R=16, start = 828+16*(bb-128)(rows  828..1035, padded)
__global__ void __launch_bounds__(256, 1) k_scan(const float* __restrict__ b_hh,
                                                 const int* __restrict__ lengths) {
    __shared__ float hs[Hh][18];
    int bb = blockIdx.x;
    if (bb < 48)        scan_body<4>(hs, 4 * bb, b_hh, lengths);
    else if (bb < 80)   scan_body<6>(hs, 192 + 6 * (bb - 48), b_hh, lengths);
    else if (bb < 108)  scan_body<8>(hs, 384 + 8 * (bb - 80), b_hh, lengths);
    else if (bb < 128)  scan_body<11>(hs, 608 + 11 * (bb - 108), b_hh, lengths);
    else                scan_body<16>(hs, 828 + 16 * (bb - 128), b_hh, lengths);
}

// ---------------- kmeans -----------------------------------------------------
__global__ void k_cinit(IdxList il) {
    int d = threadIdx.x;
#pragma unroll
    for (int k = 0; k < KK; k++)
        g_centers[k * Hh + d] = g_hA[(size_t)il.v[k] * Hh + d];
}

__global__ void k_assign() {
    __shared__ float cs[KK * Hh];
    int tid = threadIdx.x;  // 128
    for (int i = tid; i < KK * Hh; i += 128) cs[i] = g_centers[i];
    __syncthreads();

    int warp = tid >> 5, lane = tid & 31;
    int b = blockIdx.x * 4 + warp;

    float dist[KK];
#pragma unroll
    for (int k = 0; k < KK; k++) dist[k] = 0.0f;
#pragma unroll
    for (int i = 0; i < 8; i++) {
        int d = lane + i * 32;
        float v = g_hA[(size_t)b * Hh + d];
#pragma unroll
        for (int k = 0; k < KK; k++) {
            float df = v - cs[k * Hh + d];
            dist[k] += df * df;
        }
    }
#pragma unroll
    for (int k = 0; k < KK; k++)
#pragma unroll
        for (int o = 16; o > 0; o >>= 1)
            dist[k] += __shfl_xor_sync(0xffffffffu, dist[k], o);

    int code = 0;
    float best = dist[0];
#pragma unroll
    for (int k = 1; k < KK; k++)
        if (dist[k] < best) { best = dist[k]; code = k; }
    if (lane == 0) g_codes[b] = code;
}

// deterministic update: warp 0 builds ascending member list via ballot,
// then 256 threads (one per d) sum only matching rows.
__global__ void k_update() {
    __shared__ int list[Bsz];
    __shared__ int cnt_s;
    const int k = blockIdx.x, tid = threadIdx.x;

    if (tid < 32) {
        int cnt = 0;
        for (int base = 0; base < Bsz; base += 32) {
            int code = g_codes[base + tid];
            unsigned m = __ballot_sync(0xffffffffu, code == k);
            int pos = cnt + __popc(m & ((1u << tid) - 1u));
            if (code == k) list[pos] = base + tid;
            cnt += __popc(m);
        }
        if (tid == 0) cnt_s = cnt;
    }
    __syncthreads();

    const int cnt = cnt_s;
    const int d = tid;
    float s = 0.0f;
#pragma unroll 4
    for (int i = 0; i < cnt; i++)
        s += g_hA[(size_t)list[i] * Hh + d];
    float cold = g_centers[k * Hh + d];
    g_centers[k * Hh + d] = (cnt > 0) ? (s / (float)cnt) : cold;
}

// ---------------- GCN (adj = I -> per-center MLP) ----------------------------
__global__ void k_hprime(const float* __restrict__ g1w, const float* __restrict__ g1b,
                         const float* __restrict__ g2w, const float* __restrict__ g2b) {
    int k = blockIdx.x, j = threadIdx.x;
    __shared__ float c[Hh], tmp[Hh];
    c[j] = g_centers[k * Hh + j];
    __syncthreads();
    float s = g1b[j];
    for (int d = 0; d < Hh; d++) s += c[d] * g1w[(size_t)d * Hh + j];
    tmp[j] = fmaxf(s, 0.0f);
    __syncthreads();
    float s2 = g2b[j];
    for (int d = 0; d < Hh; d++) s2 += tmp[d] * g2w[(size_t)d * Hh + j];
    g_hprime[k * Hh + j] = fmaxf(s2, 0.0f);
}

// ---------------- epilogue ---------------------------------------------------
__global__ void k_epi(const float* __restrict__ wt1w, const float* __restrict__ wt1b,
                      const float* __restrict__ wt2w, const float* __restrict__ wt2b,
                      float* __restrict__ out) {
    __shared__ float cs[KK * Hh], hp[KK * Hh], w1s[Hh], w2s[Hh];
    int tid = threadIdx.x;  // 128
    for (int i = tid; i < KK * Hh; i += 128) { cs[i] = g_centers[i]; hp[i] = g_hprime[i]; }
    for (int i = tid; i < Hh; i += 128)      { w1s[i] = wt1w[i]; w2s[i] = wt2w[i]; }
    __syncthreads();

    int warp = tid >> 5, lane = tid & 31;
    int b = blockIdx.x * 4 + warp;

    float e[KK];
#pragma unroll
    for (int k = 0; k < KK; k++) e[k] = 0.0f;
    float hv[8];
#pragma unroll
    for (int i = 0; i < 8; i++) {
        int d = lane + i * 32;
        float v = g_hA[(size_t)b * Hh + d];
        hv[i] = v;
#pragma unroll
        for (int k = 0; k < KK; k++) e[k] += v * cs[k * Hh + d];
    }
#pragma unroll
    for (int k = 0; k < KK; k++)
#pragma unroll
        for (int o = 16; o > 0; o >>= 1)
            e[k] += __shfl_xor_sync(0xffffffffu, e[k], o);

    float mx = 0.0f;
#pragma unroll
    for (int k = 0; k < KK; k++) { e[k] = fmaxf(e[k], 0.0f); mx = fmaxf(mx, e[k]); }
    float den = 0.0f, sc[KK];
#pragma unroll
    for (int k = 0; k < KK; k++) { sc[k] = expf(e[k] - mx); den += sc[k]; }
    float inv = 1.0f / den;
#pragma unroll
    for (int k = 0; k < KK; k++) sc[k] *= inv;

    float w1p = 0.0f, w2p = 0.0f, cl[8];
#pragma unroll
    for (int i = 0; i < 8; i++) {
        int d = lane + i * 32;
        float s = 0.0f;
#pragma unroll
        for (int k = 0; k < KK; k++) s += sc[k] * hp[k * Hh + d];
        cl[i] = s;
        w1p += s * w1s[d];
        w2p += hv[i] * w2s[d];
    }
#pragma unroll
    for (int o = 16; o > 0; o >>= 1) {
        w1p += __shfl_xor_sync(0xffffffffu, w1p, o);
        w2p += __shfl_xor_sync(0xffffffffu, w2p, o);
    }
    float w1 = 1.0f / (1.0f + expf(-(w1p + wt1b[0])));
    float w2 = 1.0f / (1.0f + expf(-(w2p + wt2b[0])));
    float w1n = w1 / (w1 + w2 + 1e-8f);
#pragma unroll
    for (int i = 0; i < 8; i++) {
        int d = lane + i * 32;
        out[(size_t)b * Hh + d] = w1n * cl[i] + (1.0f - w1n) * hv[i];
    }
}

// ---------------- host: JAX threefry replication -----------------------------
static inline uint32_t rotl32(uint32_t v, int d) { return (v << d) | (v >> (32 - d)); }

static void threefry2x32(uint32_t k0, uint32_t k1, uint32_t c0, uint32_t c1,
                         uint32_t* o0, uint32_t* o1) {
    uint32_t ks0 = k0, ks1 = k1, ks2 = k0 ^ k1 ^ 0x1BD11BDAu;
    uint32_t x0 = c0 + ks0, x1 = c1 + ks1;
    const int rA[4] = {13, 15, 26, 6};
    const int rB[4] = {17, 29, 16, 24};
#define TF4(R) for (int i_ = 0; i_ < 4; i_++) { x0 += x1; x1 = rotl32(x1, R[i_]); x1 ^= x0; }
    TF4(rA); x0 += ks1; x1 += ks2 + 1u;
    TF4(rB); x0 += ks2; x1 += ks0 + 2u;
    TF4(rA); x0 += ks0; x1 += ks1 + 3u;
    TF4(rB); x0 += ks1; x1 += ks2 + 4u;
    TF4(rA); x0 += ks2; x1 += ks0 + 5u;
#undef TF4
    *o0 = x0; *o1 = x1;
}

static void compute_init_indices(int* out12) {
    uint32_t sk0, sk1;
    threefry2x32(0u, 42u, 0u, 1u, &sk0, &sk1);
    uint32_t keys[Bsz];
    for (int i = 0; i < Bsz; i++) {
        uint32_t o0, o1;
        threefry2x32(sk0, sk1, 0u, (uint32_t)i, &o0, &o1);
        keys[i] = o0 ^ o1;
    }
    int idx[Bsz];
    for (int i = 0; i < Bsz; i++) idx[i] = i;
    std::stable_sort(idx, idx + Bsz,
                     [&](int a, int b) { return keys[a] < keys[b]; });
    for (int k = 0; k < KK; k++) out12[k] = idx[k];
}

// ---------------- launch -----------------------------------------------------
extern "C" void kernel_launch(void* const* d_in, const int* in_sizes, int n_in,
                              void* d_out, int out_size) {
    const float* x       = (const float*)d_in[0];
    const int*   lengths = (const int*)  d_in[1];
    const float* w_ih    = (const float*)d_in[2];
    const float* w_hh    = (const float*)d_in[3];
    const float* b_ih    = (const float*)d_in[4];
    const float* b_hh    = (const float*)d_in[5];
    const float* g1w     = (const float*)d_in[6];
    const float* g1b     = (const float*)d_in[7];
    const float* g2w     = (const float*)d_in[8];
    const float* g2b     = (const float*)d_in[9];
    const float* wt1w    = (const float*)d_in[10];
    const float* wt1b    = (const float*)d_in[11];
    const float* wt2w    = (const float*)d_in[12];
    const float* wt2b    = (const float*)d_in[13];
    float* out = (float*)d_out;
    (void)in_sizes; (void)n_in; (void)out_size;

    IdxList il;
    compute_init_indices(il.v);

    k_init<<<1024, 256>>>();
    k_trans<<<(G3H * Hh + 255) / 256, 256>>>(w_hh);
    k_sort<<<1, 256>>>(lengths);
    k_xproj<<<dim3(12, 1600), 256>>>(x, w_ih, b_ih, lengths);
    k_scan<<<NSCAN, 256>>>(b_hh, lengths);
    k_cinit<<<1, 256>>>(il);
    for (int it = 0; it < KMI; it++) {
        k_assign<<<256, 128>>>();
        k_update<<<KK, 256>>>();
    }
    k_hprime<<<KK, 256>>>(g1w, g1b, g2w, g2b);
    k_epi<<<256, 128>>>(wt1w, wt1b, wt2w, wt2b, out);
}

// round 11
// speedup vs baseline: 1.5494x; 1.1866x over previous
#include <cuda_runtime.h>
#include <stdint.h>
#include <math.h>
#include <algorithm>

#define Bsz 1024
#define Tt  200
#define Dd  512
#define Hh  256
#define KK  12
#define KMI 30
#define G3H 768
#define NSCAN 141

// ---------------- scratch ----------------------------------------------------
__device__ float g_xproj[(size_t)Tt * Bsz * G3H];  // [T][B][3H]
// packed recurrence weights: g_wv4[(kq*3+g)*Hh + j] = w_hh[g*256+j][4kq..4kq+3]
// +1 kq group of padding so the software prefetch can read one group ahead.
__device__ float4 g_wv4[((Hh / 4) + 1) * 3 * Hh];
__device__ float g_hA[Bsz * Hh];
__device__ float g_centers[KK * Hh];
__device__ float g_hprime[KK * Hh];
__device__ int   g_codes[Bsz];
__device__ int   g_order[Bsz];    // row indices sorted by length desc

struct IdxList { int v[KK]; };

__global__ void k_init() {
    int idx = blockIdx.x * blockDim.x + threadIdx.x;
    if (idx < Bsz * Hh) g_hA[idx] = 0.0f;
}

// ---------------- repack w_hh: [3H][H] -> float4-blocked ---------------------
__global__ void k_trans(const float* __restrict__ w_hh) {
    int idx = blockIdx.x * 256 + threadIdx.x;
    if (idx < G3H * Hh) {
        int n = idx / Hh, k = idx - n * Hh;  // w_hh[n][k]
        int g = n >> 8, j = n & 255;
        int kq = k >> 2, kr = k & 3;
        reinterpret_cast<float*>(g_wv4)[(size_t)(((kq * 3) + g) * Hh + j) * 4 + kr] =
            w_hh[idx];
    }
}

// ---------------- rank-sort rows by length desc -------------------------------
__global__ void k_sort(const int* __restrict__ lengths) {
    __shared__ int ls[Bsz];
    int tid = threadIdx.x;
    for (int i = tid; i < Bsz; i += 256) ls[i] = lengths[i];
    __syncthreads();
    for (int i = tid; i < Bsz; i += 256) {
        int li = ls[i];
        int r = 0;
        for (int b = 0; b < Bsz; b++) {
            int lb = ls[b];
            r += (lb > li) || (lb == li && b < i);
        }
        g_order[r] = i;
    }
}

// ---------------- tf32 helpers ------------------------------------------------
__device__ __forceinline__ uint32_t f2tf32(float f) {
    uint32_t r;
    asm("cvt.rna.tf32.f32 %0, %1;" : "=r"(r) : "f"(f));
    return r;
}
__device__ __forceinline__ void split_tf32(float f, uint32_t& hi, uint32_t& lo) {
    hi = f2tf32(f);
    lo = f2tf32(f - __uint_as_float(hi));
}
__device__ __forceinline__ void mma_tf32(float* c, const uint32_t* a,
                                         const uint32_t* b) {
    asm volatile(
        "mma.sync.aligned.m16n8k8.row.col.f32.tf32.tf32.f32 "
        "{%0,%1,%2,%3}, {%4,%5,%6,%7}, {%8,%9}, {%0,%1,%2,%3};"
        : "+f"(c[0]), "+f"(c[1]), "+f"(c[2]), "+f"(c[3])
        : "r"(a[0]), "r"(a[1]), "r"(a[2]), "r"(a[3]), "r"(b[0]), "r"(b[1]));
}

// ---------------- packed f32x2 helpers (Blackwell FFMA2) ---------------------
typedef unsigned long long u64;
__device__ __forceinline__ void fma2(u64& acc, u64 a, u64 b) {
    asm("fma.rn.f32x2 %0, %1, %2, %3;" : "=l"(acc) : "l"(a), "l"(b), "l"(acc));
}
__device__ __forceinline__ void unpack2(u64 v, float& lo, float& hi) {
    asm("mov.b64 {%0, %1}, %2;" : "=f"(lo), "=f"(hi) : "l"(v));
}

// ---------------- x-projection GEMM (tensor cores, 3xTF32, double-buffered) --
__global__ void __launch_bounds__(256, 3) k_xproj(const float* __restrict__ x,
                                                  const float* __restrict__ w_ih,
                                                  const float* __restrict__ b_ih,
                                                  const int* __restrict__ lengths) {
    const int m0 = blockIdx.y * 128;
    const int n0 = blockIdx.x * 64;

    {   // skip block if no covered (b,t) is ever consumed
        int b_first = m0 / Tt, b_last = (m0 + 127) / Tt;
        bool need = false;
        for (int b = b_first; b <= b_last && b < Bsz; b++) {
            int t_start = (m0 > b * Tt) ? (m0 - b * Tt) : 0;
            if (lengths[b] > t_start) need = true;
        }
        if (!need) return;
    }

    __shared__ float As[2][16][132];   // fp32, split to tf32 in registers
    __shared__ float Bs[2][16][68];

    const int tid = threadIdx.x;
    const int lr = tid >> 2, lc4 = tid & 3;
    const int wid = tid >> 5, lane = tid & 31;
    const int wm = (wid & 3) * 32;
    const int wn = (wid >> 2) * 32;
    const int lq = lane >> 2, lc = lane & 3;

    float c[2][4][4];
#pragma unroll
    for (int mf = 0; mf < 2; mf++)
#pragma unroll
        for (int nf = 0; nf < 4; nf++)
#pragma unroll
            for (int q = 0; q < 4; q++) c[mf][nf][q] = 0.0f;

    {
        float4 v0 = *reinterpret_cast<const float4*>(
            &x[(size_t)(m0 + lr) * Dd + lc4 * 4]);
        float4 v1 = *reinterpret_cast<const float4*>(
            &x[(size_t)(m0 + lr + 64) * Dd + lc4 * 4]);
        float4 vb = *reinterpret_cast<const float4*>(
            &w_ih[(size_t)(n0 + lr) * Dd + lc4 * 4]);
        As[0][lc4 * 4 + 0][lr] = v0.x; As[0][lc4 * 4 + 1][lr] = v0.y;
        As[0][lc4 * 4 + 2][lr] = v0.z; As[0][lc4 * 4 + 3][lr] = v0.w;
        As[0][lc4 * 4 + 0][lr + 64] = v1.x; As[0][lc4 * 4 + 1][lr + 64] = v1.y;
        As[0][lc4 * 4 + 2][lr + 64] = v1.z; As[0][lc4 * 4 + 3][lr + 64] = v1.w;
        Bs[0][lc4 * 4 + 0][lr] = vb.x; Bs[0][lc4 * 4 + 1][lr] = vb.y;
        Bs[0][lc4 * 4 + 2][lr] = vb.z; Bs[0][lc4 * 4 + 3][lr] = vb.w;
    }
    __syncthreads();

    int buf = 0;
    for (int k0 = 0; k0 < Dd; k0 += 16) {
        const bool has_next = (k0 + 16 < Dd);
        float4 pa0, pa1, pb;
        if (has_next) {
            pa0 = *reinterpret_cast<const float4*>(
                &x[(size_t)(m0 + lr) * Dd + k0 + 16 + lc4 * 4]);
            pa1 = *reinterpret_cast<const float4*>(
                &x[(size_t)(m0 + lr + 64) * Dd + k0 + 16 + lc4 * 4]);
            pb = *reinterpret_cast<const float4*>(
                &w_ih[(size_t)(n0 + lr) * Dd + k0 + 16 + lc4 * 4]);
        }

#pragma unroll
        for (int ks = 0; ks < 2; ks++) {
            const int kb = ks * 8;
            uint32_t ah[2][4], al[2][4];
#pragma unroll
            for (int mf = 0; mf < 2; mf++) {
                int r = wm + mf * 16 + lq;
                float f0 = As[buf][kb + lc][r];
                float f1 = As[buf][kb + lc][r + 8];
                float f2 = As[buf][kb + lc + 4][r];
                float f3 = As[buf][kb + lc + 4][r + 8];
                split_tf32(f0, ah[mf][0], al[mf][0]);
                split_tf32(f1, ah[mf][1], al[mf][1]);
                split_tf32(f2, ah[mf][2], al[mf][2]);
                split_tf32(f3, ah[mf][3], al[mf][3]);
            }
            uint32_t bh[4][2], bl[4][2];
#pragma unroll
            for (int nf = 0; nf < 4; nf++) {
                int n = wn + nf * 8 + lq;
                float f0 = Bs[buf][kb + lc][n];
                float f1 = Bs[buf][kb + lc + 4][n];
                split_tf32(f0, bh[nf][0], bl[nf][0]);
                split_tf32(f1, bh[nf][1], bl[nf][1]);
            }
#pragma unroll
            for (int mf = 0; mf < 2; mf++)
#pragma unroll
                for (int nf = 0; nf < 4; nf++) {
                    mma_tf32(c[mf][nf], ah[mf], bh[nf]);  // hi*hi
                    mma_tf32(c[mf][nf], ah[mf], bl[nf]);  // hi*lo
                    mma_tf32(c[mf][nf], al[mf], bh[nf]);  // lo*hi
                }
        }

        if (has_next) {
            int nb = buf ^ 1;
            As[nb][lc4 * 4 + 0][lr] = pa0.x; As[nb][lc4 * 4 + 1][lr] = pa0.y;
            As[nb][lc4 * 4 + 2][lr] = pa0.z; As[nb][lc4 * 4 + 3][lr] = pa0.w;
            As[nb][lc4 * 4 + 0][lr + 64] = pa1.x; As[nb][lc4 * 4 + 1][lr + 64] = pa1.y;
            As[nb][lc4 * 4 + 2][lr + 64] = pa1.z; As[nb][lc4 * 4 + 3][lr + 64] = pa1.w;
            Bs[nb][lc4 * 4 + 0][lr] = pb.x; Bs[nb][lc4 * 4 + 1][lr] = pb.y;
            Bs[nb][lc4 * 4 + 2][lr] = pb.z; Bs[nb][lc4 * 4 + 3][lr] = pb.w;
            __syncthreads();
            buf = nb;
        }
    }

#pragma unroll
    for (int mf = 0; mf < 2; mf++)
#pragma unroll
        for (int half = 0; half < 2; half++) {
            int row = m0 + wm + mf * 16 + lq + half * 8;
            int b = row / Tt;
            int t = row - b * Tt;
            size_t base = ((size_t)t * Bsz + b) * G3H + n0 + wn;
#pragma unroll
            for (int nf = 0; nf < 4; nf++) {
                int col = nf * 8 + lc * 2;
                float2 o;
                o.x = c[mf][nf][half * 2 + 0] + b_ih[n0 + wn + col];
                o.y = c[mf][nf][half * 2 + 1] + b_ih[n0 + wn + col + 1];
                *reinterpret_cast<float2*>(&g_xproj[base + col]) = o;
            }
        }
}

// ---------------- persistent GRU scan (k-paired FFMA2 + prefetch) ------------
// acc2 holds (even-k, odd-k) fp32 partials per row/gate; weights stream as
// ulonglong2 (one LDG.128 -> two u64 operands, no packing); w prefetched one
// kq group ahead; xproj gate inputs hoisted to the top of the step (R<=8).
template <int R>
__device__ void scan_body(float (*hs)[Hh], int start,
                          const float* __restrict__ b_hh,
                          const int* __restrict__ lengths) {
    const int j = threadIdx.x;

    int rows[R], lens[R];
#pragma unroll
    for (int i = 0; i < R; i++) {
        int p = start + i;
        rows[i] = (p < Bsz) ? g_order[p] : 0;
        lens[i] = (p < Bsz) ? lengths[rows[i]] : 0;
    }
#pragma unroll
    for (int i = 0; i < R; i++) hs[i][j] = 0.0f;
    __syncthreads();

    int maxlen = 0;
#pragma unroll
    for (int i = 0; i < R; i++) maxlen = max(maxlen, lens[i]);

    const float bhr = b_hh[j], bhz = b_hh[Hh + j], bhn = b_hh[2 * Hh + j];
    const ulonglong2* __restrict__ wbase =
        reinterpret_cast<const ulonglong2*>(g_wv4);

    for (int t = 0; t < maxlen; t++) {
        u64 a2r[R], a2z[R], a2n[R];
#pragma unroll
        for (int i = 0; i < R; i++) { a2r[i] = 0ull; a2z[i] = 0ull; a2n[i] = 0ull; }

        // hoisted xproj loads (register pressure permits for R<=8)
        float xr[R], xz[R], xn[R];
        if constexpr (R <= 8) {
#pragma unroll
            for (int i = 0; i < R; i++) {
                if (t < lens[i]) {
                    const float* xp =
                        &g_xproj[((size_t)t * Bsz + rows[i]) * G3H + j];
                    xr[i] = xp[0]; xz[i] = xp[Hh]; xn[i] = xp[2 * Hh];
                } else {
                    xr[i] = 0.f; xz[i] = 0.f; xn[i] = 0.f;
                }
            }
        }

        ulonglong2 wr = wbase[(0 * 3 + 0) * Hh + j];
        ulonglong2 wz = wbase[(0 * 3 + 1) * Hh + j];
        ulonglong2 wn = wbase[(0 * 3 + 2) * Hh + j];
#pragma unroll 2
        for (int kq = 0; kq < Hh / 4; kq++) {
            // prefetch next kq group (padded array makes kq=63 read safe)
            ulonglong2 wrn = wbase[((kq + 1) * 3 + 0) * Hh + j];
            ulonglong2 wzn = wbase[((kq + 1) * 3 + 1) * Hh + j];
            ulonglong2 wnn = wbase[((kq + 1) * 3 + 2) * Hh + j];
#pragma unroll
            for (int i = 0; i < R; i++) {
                ulonglong2 h2 =
                    *reinterpret_cast<const ulonglong2*>(&hs[i][kq * 4]);
                fma2(a2r[i], h2.x, wr.x); fma2(a2r[i], h2.y, wr.y);
                fma2(a2z[i], h2.x, wz.x); fma2(a2z[i], h2.y, wz.y);
                fma2(a2n[i], h2.x, wn.x); fma2(a2n[i], h2.y, wn.y);
            }
            wr = wrn; wz = wzn; wn = wnn;
        }

        float hnew[R];
#pragma unroll
        for (int i = 0; i < R; i++) {
            float hold = hs[i][j];
            if (t < lens[i]) {
                float lo, hi;
                unpack2(a2r[i], lo, hi); float arv = lo + hi;
                unpack2(a2z[i], lo, hi); float azv = lo + hi;
                unpack2(a2n[i], lo, hi); float anv = lo + hi;
                float xrv, xzv, xnv;
                if constexpr (R <= 8) {
                    xrv = xr[i]; xzv = xz[i]; xnv = xn[i];
                } else {
                    const float* xp =
                        &g_xproj[((size_t)t * Bsz + rows[i]) * G3H + j];
                    xrv = xp[0]; xzv = xp[Hh]; xnv = xp[2 * Hh];
                }
                float r = 1.0f / (1.0f + expf(-(xrv + arv + bhr)));
                float z = 1.0f / (1.0f + expf(-(xzv + azv + bhz)));
                float n = tanhf(xnv + r * (anv + bhn));
                hnew[i] = (1.0f - z) * n + z * hold;
            } else {
                hnew[i] = hold;
            }
        }
        __syncthreads();
#pragma unroll
        for (int i = 0; i < R; i++) hs[i][j] = hnew[i];
        __syncthreads();
    }

#pragma unroll
    for (int i = 0; i < R; i++)
        if (start + i < Bsz)
            g_hA[(size_t)rows[i] * Hh + j] = hs[i][j];
}

// Static schedule over sorted ranks (uniform-length order statistics):
//   bb   0..47 : R=4,  start = 4*bb           (rows    0..191)
//   bb  48..79 : R=6,  start = 192+6*(bb-48)  (rows  192..383)
//   bb  80..107: R=8,  start = 384+8*(bb-80)  (rows  384..607)
//   bb 108..127: R=11, start = 608+11*(bb-108)(rows  608..827)
//   bb 128..140: R=16, start = 828+16*(bb-128)(rows  828..1035, padded)
__global__ void __launch_bounds__(256, 1) k_scan(const float* __restrict__ b_hh,
                                                 const int* __restrict__ lengths) {
    __shared__ float hs[16][Hh];
    int bb = blockIdx.x;
    if (bb < 48)        scan_body<4>(hs, 4 * bb, b_hh, lengths);
    else if (bb < 80)   scan_body<6>(hs, 192 + 6 * (bb - 48), b_hh, lengths);
    else if (bb < 108)  scan_body<8>(hs, 384 + 8 * (bb - 80), b_hh, lengths);
    else if (bb < 128)  scan_body<11>(hs, 608 + 11 * (bb - 108), b_hh, lengths);
    else                scan_body<16>(hs, 828 + 16 * (bb - 128), b_hh, lengths);
}

// ---------------- kmeans -----------------------------------------------------
__global__ void k_cinit(IdxList il) {
    int d = threadIdx.x;
#pragma unroll
    for (int k = 0; k < KK; k++)
        g_centers[k * Hh + d] = g_hA[(size_t)il.v[k] * Hh + d];
}

__global__ void k_assign() {
    __shared__ float cs[KK * Hh];
    int tid = threadIdx.x;  // 128
    for (int i = tid; i < KK * Hh; i += 128) cs[i] = g_centers[i];
    __syncthreads();

    int warp = tid >> 5, lane = tid & 31;
    int b = blockIdx.x * 4 + warp;

    float dist[KK];
#pragma unroll
    for (int k = 0; k < KK; k++) dist[k] = 0.0f;
#pragma unroll
    for (int i = 0; i < 8; i++) {
        int d = lane + i * 32;
        float v = g_hA[(size_t)b * Hh + d];
#pragma unroll
        for (int k = 0; k < KK; k++) {
            float df = v - cs[k * Hh + d];
            dist[k] += df * df;
        }
    }
#pragma unroll
    for (int k = 0; k < KK; k++)
#pragma unroll
        for (int o = 16; o > 0; o >>= 1)
            dist[k] += __shfl_xor_sync(0xffffffffu, dist[k], o);

    int code = 0;
    float best = dist[0];
#pragma unroll
    for (int k = 1; k < KK; k++)
        if (dist[k] < best) { best = dist[k]; code = k; }
    if (lane == 0) g_codes[b] = code;
}

// deterministic update: warp 0 builds ascending member list via ballot,
// then 256 threads (one per d) sum only matching rows.
__global__ void k_update() {
    __shared__ int list[Bsz];
    __shared__ int cnt_s;
    const int k = blockIdx.x, tid = threadIdx.x;

    if (tid < 32) {
        int cnt = 0;
        for (int base = 0; base < Bsz; base += 32) {
            int code = g_codes[base + tid];
            unsigned m = __ballot_sync(0xffffffffu, code == k);
            int pos = cnt + __popc(m & ((1u << tid) - 1u));
            if (code == k) list[pos] = base + tid;
            cnt += __popc(m);
        }
        if (tid == 0) cnt_s = cnt;
    }
    __syncthreads();

    const int cnt = cnt_s;
    const int d = tid;
    float s = 0.0f;
#pragma unroll 4
    for (int i = 0; i < cnt; i++)
        s += g_hA[(size_t)list[i] * Hh + d];
    float cold = g_centers[k * Hh + d];
    g_centers[k * Hh + d] = (cnt > 0) ? (s / (float)cnt) : cold;
}

// ---------------- GCN (adj = I -> per-center MLP) ----------------------------
__global__ void k_hprime(const float* __restrict__ g1w, const float* __restrict__ g1b,
                         const float* __restrict__ g2w, const float* __restrict__ g2b) {
    int k = blockIdx.x, j = threadIdx.x;
    __shared__ float c[Hh], tmp[Hh];
    c[j] = g_centers[k * Hh + j];
    __syncthreads();
    float s = g1b[j];
    for (int d = 0; d < Hh; d++) s += c[d] * g1w[(size_t)d * Hh + j];
    tmp[j] = fmaxf(s, 0.0f);
    __syncthreads();
    float s2 = g2b[j];
    for (int d = 0; d < Hh; d++) s2 += tmp[d] * g2w[(size_t)d * Hh + j];
    g_hprime[k * Hh + j] = fmaxf(s2, 0.0f);
}

// ---------------- epilogue ---------------------------------------------------
__global__ void k_epi(const float* __restrict__ wt1w, const float* __restrict__ wt1b,
                      const float* __restrict__ wt2w, const float* __restrict__ wt2b,
                      float* __restrict__ out) {
    __shared__ float cs[KK * Hh], hp[KK * Hh], w1s[Hh], w2s[Hh];
    int tid = threadIdx.x;  // 128
    for (int i = tid; i < KK * Hh; i += 128) { cs[i] = g_centers[i]; hp[i] = g_hprime[i]; }
    for (int i = tid; i < Hh; i += 128)      { w1s[i] = wt1w[i]; w2s[i] = wt2w[i]; }
    __syncthreads();

    int warp = tid >> 5, lane = tid & 31;
    int b = blockIdx.x * 4 + warp;

    float e[KK];
#pragma unroll
    for (int k = 0; k < KK; k++) e[k] = 0.0f;
    float hv[8];
#pragma unroll
    for (int i = 0; i < 8; i++) {
        int d = lane + i * 32;
        float v = g_hA[(size_t)b * Hh + d];
        hv[i] = v;
#pragma unroll
        for (int k = 0; k < KK; k++) e[k] += v * cs[k * Hh + d];
    }
#pragma unroll
    for (int k = 0; k < KK; k++)
#pragma unroll
        for (int o = 16; o > 0; o >>= 1)
            e[k] += __shfl_xor_sync(0xffffffffu, e[k], o);

    float mx = 0.0f;
#pragma unroll
    for (int k = 0; k < KK; k++) { e[k] = fmaxf(e[k], 0.0f); mx = fmaxf(mx, e[k]); }
    float den = 0.0f, sc[KK];
#pragma unroll
    for (int k = 0; k < KK; k++) { sc[k] = expf(e[k] - mx); den += sc[k]; }
    float inv = 1.0f / den;
#pragma unroll
    for (int k = 0; k < KK; k++) sc[k] *= inv;

    float w1p = 0.0f, w2p = 0.0f, cl[8];
#pragma unroll
    for (int i = 0; i < 8; i++) {
        int d = lane + i * 32;
        float s = 0.0f;
#pragma unroll
        for (int k = 0; k < KK; k++) s += sc[k] * hp[k * Hh + d];
        cl[i] = s;
        w1p += s * w1s[d];
        w2p += hv[i] * w2s[d];
    }
#pragma unroll
    for (int o = 16; o > 0; o >>= 1) {
        w1p += __shfl_xor_sync(0xffffffffu, w1p, o);
        w2p += __shfl_xor_sync(0xffffffffu, w2p, o);
    }
    float w1 = 1.0f / (1.0f + expf(-(w1p + wt1b[0])));
    float w2 = 1.0f / (1.0f + expf(-(w2p + wt2b[0])));
    float w1n = w1 / (w1 + w2 + 1e-8f);
#pragma unroll
    for (int i = 0; i < 8; i++) {
        int d = lane + i * 32;
        out[(size_t)b * Hh + d] = w1n * cl[i] + (1.0f - w1n) * hv[i];
    }
}

// ---------------- host: JAX threefry replication -----------------------------
static inline uint32_t rotl32(uint32_t v, int d) { return (v << d) | (v >> (32 - d)); }

static void threefry2x32(uint32_t k0, uint32_t k1, uint32_t c0, uint32_t c1,
                         uint32_t* o0, uint32_t* o1) {
    uint32_t ks0 = k0, ks1 = k1, ks2 = k0 ^ k1 ^ 0x1BD11BDAu;
    uint32_t x0 = c0 + ks0, x1 = c1 + ks1;
    const int rA[4] = {13, 15, 26, 6};
    const int rB[4] = {17, 29, 16, 24};
#define TF4(R) for (int i_ = 0; i_ < 4; i_++) { x0 += x1; x1 = rotl32(x1, R[i_]); x1 ^= x0; }
    TF4(rA); x0 += ks1; x1 += ks2 + 1u;
    TF4(rB); x0 += ks2; x1 += ks0 + 2u;
    TF4(rA); x0 += ks0; x1 += ks1 + 3u;
    TF4(rB); x0 += ks1; x1 += ks2 + 4u;
    TF4(rA); x0 += ks2; x1 += ks0 + 5u;
#undef TF4
    *o0 = x0; *o1 = x1;
}

static void compute_init_indices(int* out12) {
    uint32_t sk0, sk1;
    threefry2x32(0u, 42u, 0u, 1u, &sk0, &sk1);
    uint32_t keys[Bsz];
    for (int i = 0; i < Bsz; i++) {
        uint32_t o0, o1;
        threefry2x32(sk0, sk1, 0u, (uint32_t)i, &o0, &o1);
        keys[i] = o0 ^ o1;
    }
    int idx[Bsz];
    for (int i = 0; i < Bsz; i++) idx[i] = i;
    std::stable_sort(idx, idx + Bsz,
                     [&](int a, int b) { return keys[a] < keys[b]; });
    for (int k = 0; k < KK; k++) out12[k] = idx[k];
}

// ---------------- launch -----------------------------------------------------
extern "C" void kernel_launch(void* const* d_in, const int* in_sizes, int n_in,
                              void* d_out, int out_size) {
    const float* x       = (const float*)d_in[0];
    const int*   lengths = (const int*)  d_in[1];
    const float* w_ih    = (const float*)d_in[2];
    const float* w_hh    = (const float*)d_in[3];
    const float* b_ih    = (const float*)d_in[4];
    const float* b_hh    = (const float*)d_in[5];
    const float* g1w     = (const float*)d_in[6];
    const float* g1b     = (const float*)d_in[7];
    const float* g2w     = (const float*)d_in[8];
    const float* g2b     = (const float*)d_in[9];
    const float* wt1w    = (const float*)d_in[10];
    const float* wt1b    = (const float*)d_in[11];
    const float* wt2w    = (const float*)d_in[12];
    const float* wt2b    = (const float*)d_in[13];
    float* out = (float*)d_out;
    (void)in_sizes; (void)n_in; (void)out_size;

    IdxList il;
    compute_init_indices(il.v);

    k_init<<<1024, 256>>>();
    k_trans<<<(G3H * Hh + 255) / 256, 256>>>(w_hh);
    k_sort<<<1, 256>>>(lengths);
    k_xproj<<<dim3(12, 1600), 256>>>(x, w_ih, b_ih, lengths);
    k_scan<<<NSCAN, 256>>>(b_hh, lengths);
    k_cinit<<<1, 256>>>(il);
    for (int it = 0; it < KMI; it++) {
        k_assign<<<256, 128>>>();
        k_update<<<KK, 256>>>();
    }
    k_hprime<<<KK, 256>>>(g1w, g1b, g2w, g2b);
    k_epi<<<256, 128>>>(wt1w, wt1b, wt2w, wt2b, out);
}

// round 12
// speedup vs baseline: 2.0657x; 1.3332x over previous
#include <cuda_runtime.h>
#include <stdint.h>
#include <math.h>
#include <algorithm>

#define Bsz 1024
#define Tt  200
#define Dd  512
#define Hh  256
#define KK  12
#define KMI 30
#define G3H 768
#define NSCAN 141

// ---------------- scratch ----------------------------------------------------
__device__ float g_xproj[(size_t)Tt * Bsz * G3H];  // [T][B][3H]
// packed recurrence weights: g_wv4[(kq*3+g)*Hh + j] = w_hh[g*256+j][4kq..4kq+3]
// +1 kq group of padding so the software prefetch can read one group ahead.
__device__ float4 g_wv4[((Hh / 4) + 1) * 3 * Hh];
__device__ float g_hA[Bsz * Hh];
__device__ float g_centers[KK * Hh];
__device__ float g_hprime[KK * Hh];
__device__ int   g_codes[Bsz];
__device__ int   g_order[Bsz];      // row indices sorted by length desc
__device__ int   g_rowidx[Tt * Bsz];  // compacted alive rows (m = b*T + t)
__device__ int   g_nalive;

struct IdxList { int v[KK]; };

__global__ void k_init() {
    int idx = blockIdx.x * blockDim.x + threadIdx.x;
    if (idx < Bsz * Hh) g_hA[idx] = 0.0f;
    if (idx == 0) g_nalive = 0;
}

// ---------------- alive-row compaction ---------------------------------------
__global__ void k_alive(const int* __restrict__ lengths) {
    int m = blockIdx.x * 256 + threadIdx.x;
    if (m >= Tt * Bsz) return;
    int b = m / Tt, t = m - b * Tt;
    bool alive = (t < lengths[b]);
    unsigned mask = __ballot_sync(0xffffffffu, alive);
    int lane = threadIdx.x & 31;
    int base = 0;
    if (lane == 0) base = atomicAdd(&g_nalive, __popc(mask));
    base = __shfl_sync(0xffffffffu, base, 0);
    if (alive) g_rowidx[base + __popc(mask & ((1u << lane) - 1u))] = m;
}

// ---------------- repack w_hh: [3H][H] -> float4-blocked ---------------------
__global__ void k_trans(const float* __restrict__ w_hh) {
    int idx = blockIdx.x * 256 + threadIdx.x;
    if (idx < G3H * Hh) {
        int n = idx / Hh, k = idx - n * Hh;  // w_hh[n][k]
        int g = n >> 8, j = n & 255;
        int kq = k >> 2, kr = k & 3;
        reinterpret_cast<float*>(g_wv4)[(size_t)(((kq * 3) + g) * Hh + j) * 4 + kr] =
            w_hh[idx];
    }
}

// ---------------- rank-sort rows by length desc -------------------------------
__global__ void k_sort(const int* __restrict__ lengths) {
    __shared__ int ls[Bsz];
    int tid = threadIdx.x;
    for (int i = tid; i < Bsz; i += 256) ls[i] = lengths[i];
    __syncthreads();
    for (int i = tid; i < Bsz; i += 256) {
        int li = ls[i];
        int r = 0;
        for (int b = 0; b < Bsz; b++) {
            int lb = ls[b];
            r += (lb > li) || (lb == li && b < i);
        }
        g_order[r] = i;
    }
}

// ---------------- tf32 helpers ------------------------------------------------
__device__ __forceinline__ uint32_t f2tf32(float f) {
    uint32_t r;
    asm("cvt.rna.tf32.f32 %0, %1;" : "=r"(r) : "f"(f));
    return r;
}
__device__ __forceinline__ void split_tf32(float f, uint32_t& hi, uint32_t& lo) {
    hi = f2tf32(f);
    lo = f2tf32(f - __uint_as_float(hi));
}
__device__ __forceinline__ void mma_tf32(float* c, const uint32_t* a,
                                         const uint32_t* b) {
    asm volatile(
        "mma.sync.aligned.m16n8k8.row.col.f32.tf32.tf32.f32 "
        "{%0,%1,%2,%3}, {%4,%5,%6,%7}, {%8,%9}, {%0,%1,%2,%3};"
        : "+f"(c[0]), "+f"(c[1]), "+f"(c[2]), "+f"(c[3])
        : "r"(a[0]), "r"(a[1]), "r"(a[2]), "r"(a[3]), "r"(b[0]), "r"(b[1]));
}

// ---------------- packed f32x2 helpers (Blackwell FFMA2) ---------------------
typedef unsigned long long u64;
__device__ __forceinline__ void fma2(u64& acc, u64 a, u64 b) {
    asm("fma.rn.f32x2 %0, %1, %2, %3;" : "=l"(acc) : "l"(a), "l"(b), "l"(acc));
}
__device__ __forceinline__ void unpack2(u64 v, float& lo, float& hi) {
    asm("mov.b64 {%0, %1}, %2;" : "=f"(lo), "=f"(hi) : "l"(v));
}

// ---------------- x-projection GEMM (compacted rows, 3xTF32, dbuf) -----------
__global__ void __launch_bounds__(256, 3) k_xproj(const float* __restrict__ x,
                                                  const float* __restrict__ w_ih,
                                                  const float* __restrict__ b_ih) {
    const int m0 = blockIdx.y * 128;
    const int n0 = blockIdx.x * 64;
    const int nalive = g_nalive;
    if (m0 >= nalive) return;

    __shared__ float As[2][16][132];   // fp32, split to tf32 in registers
    __shared__ float Bs[2][16][68];

    const int tid = threadIdx.x;
    const int lr = tid >> 2, lc4 = tid & 3;
    const int wid = tid >> 5, lane = tid & 31;
    const int wm = (wid & 3) * 32;
    const int wn = (wid >> 2) * 32;
    const int lq = lane >> 2, lc = lane & 3;

    // hoist compacted row indices for the two A rows this thread stages
    int rid0 = m0 + lr, rid1 = m0 + lr + 64;
    const int mrow0 = (rid0 < nalive) ? g_rowidx[rid0] : g_rowidx[0];
    const int mrow1 = (rid1 < nalive) ? g_rowidx[rid1] : g_rowidx[0];

    float c[2][4][4];
#pragma unroll
    for (int mf = 0; mf < 2; mf++)
#pragma unroll
        for (int nf = 0; nf < 4; nf++)
#pragma unroll
            for (int q = 0; q < 4; q++) c[mf][nf][q] = 0.0f;

    {
        float4 v0 = *reinterpret_cast<const float4*>(
            &x[(size_t)mrow0 * Dd + lc4 * 4]);
        float4 v1 = *reinterpret_cast<const float4*>(
            &x[(size_t)mrow1 * Dd + lc4 * 4]);
        float4 vb = *reinterpret_cast<const float4*>(
            &w_ih[(size_t)(n0 + lr) * Dd + lc4 * 4]);
        As[0][lc4 * 4 + 0][lr] = v0.x; As[0][lc4 * 4 + 1][lr] = v0.y;
        As[0][lc4 * 4 + 2][lr] = v0.z; As[0][lc4 * 4 + 3][lr] = v0.w;
        As[0][lc4 * 4 + 0][lr + 64] = v1.x; As[0][lc4 * 4 + 1][lr + 64] = v1.y;
        As[0][lc4 * 4 + 2][lr + 64] = v1.z; As[0][lc4 * 4 + 3][lr + 64] = v1.w;
        Bs[0][lc4 * 4 + 0][lr] = vb.x; Bs[0][lc4 * 4 + 1][lr] = vb.y;
        Bs[0][lc4 * 4 + 2][lr] = vb.z; Bs[0][lc4 * 4 + 3][lr] = vb.w;
    }
    __syncthreads();

    int buf = 0;
    for (int k0 = 0; k0 < Dd; k0 += 16) {
        const bool has_next = (k0 + 16 < Dd);
        float4 pa0, pa1, pb;
        if (has_next) {
            pa0 = *reinterpret_cast<const float4*>(
                &x[(size_t)mrow0 * Dd + k0 + 16 + lc4 * 4]);
            pa1 = *reinterpret_cast<const float4*>(
                &x[(size_t)mrow1 * Dd + k0 + 16 + lc4 * 4]);
            pb = *reinterpret_cast<const float4*>(
                &w_ih[(size_t)(n0 + lr) * Dd + k0 + 16 + lc4 * 4]);
        }

#pragma unroll
        for (int ks = 0; ks < 2; ks++) {
            const int kb = ks * 8;
            uint32_t ah[2][4], al[2][4];
#pragma unroll
            for (int mf = 0; mf < 2; mf++) {
                int r = wm + mf * 16 + lq;
                float f0 = As[buf][kb + lc][r];
                float f1 = As[buf][kb + lc][r + 8];
                float f2 = As[buf][kb + lc + 4][r];
                float f3 = As[buf][kb + lc + 4][r + 8];
                split_tf32(f0, ah[mf][0], al[mf][0]);
                split_tf32(f1, ah[mf][1], al[mf][1]);
                split_tf32(f2, ah[mf][2], al[mf][2]);
                split_tf32(f3, ah[mf][3], al[mf][3]);
            }
            uint32_t bh[4][2], bl[4][2];
#pragma unroll
            for (int nf = 0; nf < 4; nf++) {
                int n = wn + nf * 8 + lq;
                float f0 = Bs[buf][kb + lc][n];
                float f1 = Bs[buf][kb + lc + 4][n];
                split_tf32(f0, bh[nf][0], bl[nf][0]);
                split_tf32(f1, bh[nf][1], bl[nf][1]);
            }
#pragma unroll
            for (int mf = 0; mf < 2; mf++)
#pragma unroll
                for (int nf = 0; nf < 4; nf++) {
                    mma_tf32(c[mf][nf], ah[mf], bh[nf]);  // hi*hi
                    mma_tf32(c[mf][nf], ah[mf], bl[nf]);  // hi*lo
                    mma_tf32(c[mf][nf], al[mf], bh[nf]);  // lo*hi
                }
        }

        if (has_next) {
            int nb = buf ^ 1;
            As[nb][lc4 * 4 + 0][lr] = pa0.x; As[nb][lc4 * 4 + 1][lr] = pa0.y;
            As[nb][lc4 * 4 + 2][lr] = pa0.z; As[nb][lc4 * 4 + 3][lr] = pa0.w;
            As[nb][lc4 * 4 + 0][lr + 64] = pa1.x; As[nb][lc4 * 4 + 1][lr + 64] = pa1.y;
            As[nb][lc4 * 4 + 2][lr + 64] = pa1.z; As[nb][lc4 * 4 + 3][lr + 64] = pa1.w;
            Bs[nb][lc4 * 4 + 0][lr] = pb.x; Bs[nb][lc4 * 4 + 1][lr] = pb.y;
            Bs[nb][lc4 * 4 + 2][lr] = pb.z; Bs[nb][lc4 * 4 + 3][lr] = pb.w;
            __syncthreads();
            buf = nb;
        }
    }

#pragma unroll
    for (int mf = 0; mf < 2; mf++)
#pragma unroll
        for (int half = 0; half < 2; half++) {
            int rid = m0 + wm + mf * 16 + lq + half * 8;
            if (rid >= nalive) continue;
            int row = g_rowidx[rid];
            int b = row / Tt;
            int t = row - b * Tt;
            size_t base = ((size_t)t * Bsz + b) * G3H + n0 + wn;
#pragma unroll
            for (int nf = 0; nf < 4; nf++) {
                int col = nf * 8 + lc * 2;
                float2 o;
                o.x = c[mf][nf][half * 2 + 0] + b_ih[n0 + wn + col];
                o.y = c[mf][nf][half * 2 + 1] + b_ih[n0 + wn + col + 1];
                *reinterpret_cast<float2*>(&g_xproj[base + col]) = o;
            }
        }
}

// ---------------- persistent GRU scan (k-paired FFMA2 + prefetch) ------------
template <int R>
__device__ void scan_body(float (*hs)[Hh], int start,
                          const float* __restrict__ b_hh,
                          const int* __restrict__ lengths) {
    const int j = threadIdx.x;

    int rows[R], lens[R];
#pragma unroll
    for (int i = 0; i < R; i++) {
        int p = start + i;
        rows[i] = (p < Bsz) ? g_order[p] : 0;
        lens[i] = (p < Bsz) ? lengths[rows[i]] : 0;
    }
#pragma unroll
    for (int i = 0; i < R; i++) hs[i][j] = 0.0f;
    __syncthreads();

    int maxlen = 0;
#pragma unroll
    for (int i = 0; i < R; i++) maxlen = max(maxlen, lens[i]);

    const float bhr = b_hh[j], bhz = b_hh[Hh + j], bhn = b_hh[2 * Hh + j];
    const ulonglong2* __restrict__ wbase =
        reinterpret_cast<const ulonglong2*>(g_wv4);

    for (int t = 0; t < maxlen; t++) {
        u64 a2r[R], a2z[R], a2n[R];
#pragma unroll
        for (int i = 0; i < R; i++) { a2r[i] = 0ull; a2z[i] = 0ull; a2n[i] = 0ull; }

        float xr[R], xz[R], xn[R];
        if constexpr (R <= 8) {
#pragma unroll
            for (int i = 0; i < R; i++) {
                if (t < lens[i]) {
                    const float* xp =
                        &g_xproj[((size_t)t * Bsz + rows[i]) * G3H + j];
                    xr[i] = xp[0]; xz[i] = xp[Hh]; xn[i] = xp[2 * Hh];
                } else {
                    xr[i] = 0.f; xz[i] = 0.f; xn[i] = 0.f;
                }
            }
        }

        ulonglong2 wr = wbase[(0 * 3 + 0) * Hh + j];
        ulonglong2 wz = wbase[(0 * 3 + 1) * Hh + j];
        ulonglong2 wn = wbase[(0 * 3 + 2) * Hh + j];
#pragma unroll 2
        for (int kq = 0; kq < Hh / 4; kq++) {
            ulonglong2 wrn = wbase[((kq + 1) * 3 + 0) * Hh + j];
            ulonglong2 wzn = wbase[((kq + 1) * 3 + 1) * Hh + j];
            ulonglong2 wnn = wbase[((kq + 1) * 3 + 2) * Hh + j];
#pragma unroll
            for (int i = 0; i < R; i++) {
                ulonglong2 h2 =
                    *reinterpret_cast<const ulonglong2*>(&hs[i][kq * 4]);
                fma2(a2r[i], h2.x, wr.x); fma2(a2r[i], h2.y, wr.y);
                fma2(a2z[i], h2.x, wz.x); fma2(a2z[i], h2.y, wz.y);
                fma2(a2n[i], h2.x, wn.x); fma2(a2n[i], h2.y, wn.y);
            }
            wr = wrn; wz = wzn; wn = wnn;
        }

        float hnew[R];
#pragma unroll
        for (int i = 0; i < R; i++) {
            float hold = hs[i][j];
            if (t < lens[i]) {
                float lo, hi;
                unpack2(a2r[i], lo, hi); float arv = lo + hi;
                unpack2(a2z[i], lo, hi); float azv = lo + hi;
                unpack2(a2n[i], lo, hi); float anv = lo + hi;
                float xrv, xzv, xnv;
                if constexpr (R <= 8) {
                    xrv = xr[i]; xzv = xz[i]; xnv = xn[i];
                } else {
                    const float* xp =
                        &g_xproj[((size_t)t * Bsz + rows[i]) * G3H + j];
                    xrv = xp[0]; xzv = xp[Hh]; xnv = xp[2 * Hh];
                }
                float r = 1.0f / (1.0f + expf(-(xrv + arv + bhr)));
                float z = 1.0f / (1.0f + expf(-(xzv + azv + bhz)));
                float n = tanhf(xnv + r * (anv + bhn));
                hnew[i] = (1.0f - z) * n + z * hold;
            } else {
                hnew[i] = hold;
            }
        }
        __syncthreads();
#pragma unroll
        for (int i = 0; i < R; i++) hs[i][j] = hnew[i];
        __syncthreads();
    }

#pragma unroll
    for (int i = 0; i < R; i++)
        if (start + i < Bsz)
            g_hA[(size_t)rows[i] * Hh + j] = hs[i][j];
}

__global__ void __launch_bounds__(256, 1) k_scan(const float* __restrict__ b_hh,
                                                 const int* __restrict__ lengths) {
    __shared__ float hs[16][Hh];
    int bb = blockIdx.x;
    if (bb < 48)        scan_body<4>(hs, 4 * bb, b_hh, lengths);
    else if (bb < 80)   scan_body<6>(hs, 192 + 6 * (bb - 48), b_hh, lengths);
    else if (bb < 108)  scan_body<8>(hs, 384 + 8 * (bb - 80), b_hh, lengths);
    else if (bb < 128)  scan_body<11>(hs, 608 + 11 * (bb - 108), b_hh, lengths);
    else                scan_body<16>(hs, 828 + 16 * (bb - 128), b_hh, lengths);
}

// ---------------- kmeans -----------------------------------------------------
__global__ void k_cinit(IdxList il) {
    int d = threadIdx.x;
#pragma unroll
    for (int k = 0; k < KK; k++)
        g_centers[k * Hh + d] = g_hA[(size_t)il.v[k] * Hh + d];
}

__global__ void k_assign() {
    __shared__ float cs[KK * Hh];
    int tid = threadIdx.x;  // 128
    for (int i = tid; i < KK * Hh; i += 128) cs[i] = g_centers[i];
    __syncthreads();

    int warp = tid >> 5, lane = tid & 31;
    int b = blockIdx.x * 4 + warp;

    float dist[KK];
#pragma unroll
    for (int k = 0; k < KK; k++) dist[k] = 0.0f;
#pragma unroll
    for (int i = 0; i < 8; i++) {
        int d = lane + i * 32;
        float v = g_hA[(size_t)b * Hh + d];
#pragma unroll
        for (int k = 0; k < KK; k++) {
            float df = v - cs[k * Hh + d];
            dist[k] += df * df;
        }
    }
#pragma unroll
    for (int k = 0; k < KK; k++)
#pragma unroll
        for (int o = 16; o > 0; o >>= 1)
            dist[k] += __shfl_xor_sync(0xffffffffu, dist[k], o);

    int code = 0;
    float best = dist[0];
#pragma unroll
    for (int k = 1; k < KK; k++)
        if (dist[k] < best) { best = dist[k]; code = k; }
    if (lane == 0) g_codes[b] = code;
}

__global__ void k_update() {
    __shared__ int list[Bsz];
    __shared__ int cnt_s;
    const int k = blockIdx.x, tid = threadIdx.x;

    if (tid < 32) {
        int cnt = 0;
        for (int base = 0; base < Bsz; base += 32) {
            int code = g_codes[base + tid];
            unsigned m = __ballot_sync(0xffffffffu, code == k);
            int pos = cnt + __popc(m & ((1u << tid) - 1u));
            if (code == k) list[pos] = base + tid;
            cnt += __popc(m);
        }
        if (tid == 0) cnt_s = cnt;
    }
    __syncthreads();

    const int cnt = cnt_s;
    const int d = tid;
    float s = 0.0f;
#pragma unroll 4
    for (int i = 0; i < cnt; i++)
        s += g_hA[(size_t)list[i] * Hh + d];
    float cold = g_centers[k * Hh + d];
    g_centers[k * Hh + d] = (cnt > 0) ? (s / (float)cnt) : cold;
}

// ---------------- GCN (adj = I -> per-center MLP) ----------------------------
__global__ void k_hprime(const float* __restrict__ g1w, const float* __restrict__ g1b,
                         const float* __restrict__ g2w, const float* __restrict__ g2b) {
    int k = blockIdx.x, j = threadIdx.x;
    __shared__ float c[Hh], tmp[Hh];
    c[j] = g_centers[k * Hh + j];
    __syncthreads();
    float s = g1b[j];
    for (int d = 0; d < Hh; d++) s += c[d] * g1w[(size_t)d * Hh + j];
    tmp[j] = fmaxf(s, 0.0f);
    __syncthreads();
    float s2 = g2b[j];
    for (int d = 0; d < Hh; d++) s2 += tmp[d] * g2w[(size_t)d * Hh + j];
    g_hprime[k * Hh + j] = fmaxf(s2, 0.0f);
}

// ---------------- epilogue ---------------------------------------------------
__global__ void k_epi(const float* __restrict__ wt1w, const float* __restrict__ wt1b,
                      const float* __restrict__ wt2w, const float* __restrict__ wt2b,
                      float* __restrict__ out) {
    __shared__ float cs[KK * Hh], hp[KK * Hh], w1s[Hh], w2s[Hh];
    int tid = threadIdx.x;  // 128
    for (int i = tid; i < KK * Hh; i += 128) { cs[i] = g_centers[i]; hp[i] = g_hprime[i]; }
    for (int i = tid; i < Hh; i += 128)      { w1s[i] = wt1w[i]; w2s[i] = wt2w[i]; }
    __syncthreads();

    int warp = tid >> 5, lane = tid & 31;
    int b = blockIdx.x * 4 + warp;

    float e[KK];
#pragma unroll
    for (int k = 0; k < KK; k++) e[k] = 0.0f;
    float hv[8];
#pragma unroll
    for (int i = 0; i < 8; i++) {
        int d = lane + i * 32;
        float v = g_hA[(size_t)b * Hh + d];
        hv[i] = v;
#pragma unroll
        for (int k = 0; k < KK; k++) e[k] += v * cs[k * Hh + d];
    }
#pragma unroll
    for (int k = 0; k < KK; k++)
#pragma unroll
        for (int o = 16; o > 0; o >>= 1)
            e[k] += __shfl_xor_sync(0xffffffffu, e[k], o);

    float mx = 0.0f;
#pragma unroll
    for (int k = 0; k < KK; k++) { e[k] = fmaxf(e[k], 0.0f); mx = fmaxf(mx, e[k]); }
    float den = 0.0f, sc[KK];
#pragma unroll
    for (int k = 0; k < KK; k++) { sc[k] = expf(e[k] - mx); den += sc[k]; }
    float inv = 1.0f / den;
#pragma unroll
    for (int k = 0; k < KK; k++) sc[k] *= inv;

    float w1p = 0.0f, w2p = 0.0f, cl[8];
#pragma unroll
    for (int i = 0; i < 8; i++) {
        int d = lane + i * 32;
        float s = 0.0f;
#pragma unroll
        for (int k = 0; k < KK; k++) s += sc[k] * hp[k * Hh + d];
        cl[i] = s;
        w1p += s * w1s[d];
        w2p += hv[i] * w2s[d];
    }
#pragma unroll
    for (int o = 16; o > 0; o >>= 1) {
        w1p += __shfl_xor_sync(0xffffffffu, w1p, o);
        w2p += __shfl_xor_sync(0xffffffffu, w2p, o);
    }
    float w1 = 1.0f / (1.0f + expf(-(w1p + wt1b[0])));
    float w2 = 1.0f / (1.0f + expf(-(w2p + wt2b[0])));
    float w1n = w1 / (w1 + w2 + 1e-8f);
#pragma unroll
    for (int i = 0; i < 8; i++) {
        int d = lane + i * 32;
        out[(size_t)b * Hh + d] = w1n * cl[i] + (1.0f - w1n) * hv[i];
    }
}

// ---------------- host: JAX threefry replication -----------------------------
static inline uint32_t rotl32(uint32_t v, int d) { return (v << d) | (v >> (32 - d)); }

static void threefry2x32(uint32_t k0, uint32_t k1, uint32_t c0, uint32_t c1,
                         uint32_t* o0, uint32_t* o1) {
    uint32_t ks0 = k0, ks1 = k1, ks2 = k0 ^ k1 ^ 0x1BD11BDAu;
    uint32_t x0 = c0 + ks0, x1 = c1 + ks1;
    const int rA[4] = {13, 15, 26, 6};
    const int rB[4] = {17, 29, 16, 24};
#define TF4(R) for (int i_ = 0; i_ < 4; i_++) { x0 += x1; x1 = rotl32(x1, R[i_]); x1 ^= x0; }
    TF4(rA); x0 += ks1; x1 += ks2 + 1u;
    TF4(rB); x0 += ks2; x1 += ks0 + 2u;
    TF4(rA); x0 += ks0; x1 += ks1 + 3u;
    TF4(rB); x0 += ks1; x1 += ks2 + 4u;
    TF4(rA); x0 += ks2; x1 += ks0 + 5u;
#undef TF4
    *o0 = x0; *o1 = x1;
}

static void compute_init_indices(int* out12) {
    uint32_t sk0, sk1;
    threefry2x32(0u, 42u, 0u, 1u, &sk0, &sk1);
    uint32_t keys[Bsz];
    for (int i = 0; i < Bsz; i++) {
        uint32_t o0, o1;
        threefry2x32(sk0, sk1, 0u, (uint32_t)i, &o0, &o1);
        keys[i] = o0 ^ o1;
    }
    int idx[Bsz];
    for (int i = 0; i < Bsz; i++) idx[i] = i;
    std::stable_sort(idx, idx + Bsz,
                     [&](int a, int b) { return keys[a] < keys[b]; });
    for (int k = 0; k < KK; k++) out12[k] = idx[k];
}

// ---------------- launch -----------------------------------------------------
extern "C" void kernel_launch(void* const* d_in, const int* in_sizes, int n_in,
                              void* d_out, int out_size) {
    const float* x       = (const float*)d_in[0];
    const int*   lengths = (const int*)  d_in[1];
    const float* w_ih    = (const float*)d_in[2];
    const float* w_hh    = (const float*)d_in[3];
    const float* b_ih    = (const float*)d_in[4];
    const float* b_hh    = (const float*)d_in[5];
    const float* g1w     = (const float*)d_in[6];
    const float* g1b     = (const float*)d_in[7];
    const float* g2w     = (const float*)d_in[8];
    const float* g2b     = (const float*)d_in[9];
    const float* wt1w    = (const float*)d_in[10];
    const float* wt1b    = (const float*)d_in[11];
    const float* wt2w    = (const float*)d_in[12];
    const float* wt2b    = (const float*)d_in[13];
    float* out = (float*)d_out;
    (void)in_sizes; (void)n_in; (void)out_size;

    IdxList il;
    compute_init_indices(il.v);

    k_init<<<1024, 256>>>();
    k_alive<<<(Tt * Bsz + 255) / 256, 256>>>(lengths);
    k_trans<<<(G3H * Hh + 255) / 256, 256>>>(w_hh);
    k_sort<<<1, 256>>>(lengths);
    k_xproj<<<dim3(12, 1600), 256>>>(x, w_ih, b_ih);
    k_scan<<<NSCAN, 256>>>(b_hh, lengths);
    k_cinit<<<1, 256>>>(il);
    for (int it = 0; it < KMI; it++) {
        k_assign<<<256, 128>>>();
        k_update<<<KK, 256>>>();
    }
    k_hprime<<<KK, 256>>>(g1w, g1b, g2w, g2b);
    k_epi<<<256, 128>>>(wt1w, wt1b, wt2w, wt2b, out);
}